// round 15
// baseline (speedup 1.0000x reference)
#include <cuda_runtime.h>
#include <cuda_bf16.h>
#include <cuda_fp16.h>
#include <stdint.h>
#include <math.h>

#define NTOK 2048
#define DMODEL 1024
#define NHEAD 16
#define NKV 4
#define HEADDIM 64
#define FFN 4096
#define VOCAB 32000
#define NLAYER 4
#define SEQ 1024
#define KVDIM (NKV * HEADDIM)   // 256

#define EMB_N (VOCAB * DMODEL)
#define QW_N (NLAYER * DMODEL * DMODEL)
#define KW_N (NLAYER * KVDIM * DMODEL)
#define W1_N (NLAYER * FFN * DMODEL)

// ---------------- scratch (device globals; no runtime allocation) ----------------
__device__ float g_x[NTOK * DMODEL];
__device__ float g_q[NTOK * DMODEL];
__device__ float g_k[NTOK * KVDIM];
__device__ float g_v[NTOK * KVDIM];
__device__ float g_gate[NTOK * FFN];
__device__ float g_upraw[NTOK * FFN];
__device__ float g_p0[NTOK * DMODEL];
__device__ float g_p1[NTOK * DMODEL];

__device__ __half g_h_h[NTOK * DMODEL], g_h_l[NTOK * DMODEL];
__device__ __half g_o_h[NTOK * DMODEL], g_o_l[NTOK * DMODEL];
__device__ __half g_up_h[NTOK * FFN],  g_up_l[NTOK * FFN];

__device__ __half s_emb_w[EMB_N];
__device__ __half s_qw_w[QW_N];
__device__ __half s_kw_w[KW_N];
__device__ __half s_vw_w[KW_N];
__device__ __half s_ow_h[QW_N], s_ow_l[QW_N];
__device__ __half s_w1_w[W1_N];
__device__ __half s_w2_w[W1_N];
__device__ __half s_w3_w[W1_N];

// ---------------- helpers ----------------
__device__ __forceinline__ void cpa16(uint32_t s, const void* g) {
    asm volatile("cp.async.cg.shared.global [%0], [%1], 16;" :: "r"(s), "l"(g));
}
__device__ __forceinline__ void hsplit(float x, __half& h, __half& l) {
    h = __float2half_rn(x);
    l = __float2half_rn(x - __half2float(h));
}
__device__ __forceinline__ void mma_f16(float* d, const uint32_t* a, const uint32_t* b) {
    asm volatile(
        "mma.sync.aligned.m16n8k16.row.col.f32.f16.f16.f32 "
        "{%0,%1,%2,%3},{%4,%5,%6,%7},{%8,%9},{%0,%1,%2,%3};"
        : "+f"(d[0]), "+f"(d[1]), "+f"(d[2]), "+f"(d[3])
        : "r"(a[0]), "r"(a[1]), "r"(a[2]), "r"(a[3]), "r"(b[0]), "r"(b[1]));
}

// ---------------- pre-pass kernels ----------------
__global__ void split_w_kernel(const float* __restrict__ src,
                               __half* __restrict__ w) {
    int idx = blockIdx.x * 256 + threadIdx.x;   // float4 index
    float4 v = ((const float4*)src)[idx];
    __half2* wp = (__half2*)w;
    wp[idx * 2]     = __floats2half2_rn(v.x, v.y);
    wp[idx * 2 + 1] = __floats2half2_rn(v.z, v.w);
}
__global__ void split_w2_kernel(const float* __restrict__ src,
                                __half* __restrict__ hi,
                                __half* __restrict__ lo) {
    int idx = blockIdx.x * 256 + threadIdx.x;
    float4 v = ((const float4*)src)[idx];
    float vv[4] = {v.x, v.y, v.z, v.w};
    __half h[4], l[4];
#pragma unroll
    for (int j = 0; j < 4; j++) hsplit(vv[j], h[j], l[j]);
    __half2* hp = (__half2*)hi;
    __half2* lp = (__half2*)lo;
    hp[idx * 2]     = __half2{h[0], h[1]};
    hp[idx * 2 + 1] = __half2{h[2], h[3]};
    lp[idx * 2]     = __half2{l[0], l[1]};
    lp[idx * 2 + 1] = __half2{l[2], l[3]};
}

// ---------------- embedding gather ----------------
__global__ void embed_kernel(const int* __restrict__ ids,
                             const float* __restrict__ emb,
                             float* __restrict__ x) {
    int idx = blockIdx.x * 256 + threadIdx.x;
    int n = idx >> 8;
    int c = idx & 255;
    const float4* e4 = (const float4*)emb;
    ((float4*)x)[idx] = e4[(size_t)ids[n] * 256 + c];
}

// ---------------- RMSNorm -> f16 hi/lo planes ----------------
__global__ void rmsnorm_split_kernel(const float* __restrict__ x,
                                     const float* __restrict__ w,
                                     __half* __restrict__ hi,
                                     __half* __restrict__ lo) {
    int n = blockIdx.x;
    int tid = threadIdx.x;
    const float4* xr = (const float4*)(x + (size_t)n * DMODEL);
    float4 v = xr[tid];
    float ss = v.x * v.x + v.y * v.y + v.z * v.z + v.w * v.w;
#pragma unroll
    for (int o = 16; o > 0; o >>= 1) ss += __shfl_xor_sync(0xffffffffu, ss, o);
    __shared__ float red[8];
    if ((tid & 31) == 0) red[tid >> 5] = ss;
    __syncthreads();
    float tot = 0.f;
#pragma unroll
    for (int i = 0; i < 8; i++) tot += red[i];
    float r = rsqrtf(tot * (1.0f / DMODEL) + 1e-6f);
    float4 wv = ((const float4*)w)[tid];
    float ov[4] = {wv.x * v.x * r, wv.y * v.y * r, wv.z * v.z * r, wv.w * v.w * r};
    __half h[4], l[4];
#pragma unroll
    for (int j = 0; j < 4; j++) hsplit(ov[j], h[j], l[j]);
    __half2* hp = (__half2*)(hi + (size_t)n * DMODEL);
    __half2* lp = (__half2*)(lo + (size_t)n * DMODEL);
    hp[tid * 2]     = __half2{h[0], h[1]};
    hp[tid * 2 + 1] = __half2{h[2], h[3]};
    lp[tid * 2]     = __half2{l[0], l[1]};
    lp[tid * 2 + 1] = __half2{l[2], l[3]};
}

// ---------------- merge (x += P0 + P1) + RMSNorm -> f16 hi/lo planes ----------------
__global__ void rmsnorm_merge_split_kernel(float* __restrict__ x,
                                           const float* __restrict__ P0,
                                           const float* __restrict__ P1,
                                           const float* __restrict__ w,
                                           __half* __restrict__ hi,
                                           __half* __restrict__ lo) {
    int n = blockIdx.x;
    int tid = threadIdx.x;
    size_t base = (size_t)n * DMODEL;
    float4 v = ((const float4*)(x + base))[tid];
    float4 p0 = ((const float4*)(P0 + base))[tid];
    float4 p1 = ((const float4*)(P1 + base))[tid];
    v.x += p0.x + p1.x;
    v.y += p0.y + p1.y;
    v.z += p0.z + p1.z;
    v.w += p0.w + p1.w;
    ((float4*)(x + base))[tid] = v;
    float ss = v.x * v.x + v.y * v.y + v.z * v.z + v.w * v.w;
#pragma unroll
    for (int o = 16; o > 0; o >>= 1) ss += __shfl_xor_sync(0xffffffffu, ss, o);
    __shared__ float red[8];
    if ((tid & 31) == 0) red[tid >> 5] = ss;
    __syncthreads();
    float tot = 0.f;
#pragma unroll
    for (int i = 0; i < 8; i++) tot += red[i];
    float r = rsqrtf(tot * (1.0f / DMODEL) + 1e-6f);
    float4 wv = ((const float4*)w)[tid];
    float ov[4] = {wv.x * v.x * r, wv.y * v.y * r, wv.z * v.z * r, wv.w * v.w * r};
    __half h[4], l[4];
#pragma unroll
    for (int j = 0; j < 4; j++) hsplit(ov[j], h[j], l[j]);
    __half2* hp = (__half2*)(hi + base);
    __half2* lp = (__half2*)(lo + base);
    hp[tid * 2]     = __half2{h[0], h[1]};
    hp[tid * 2 + 1] = __half2{h[2], h[3]};
    lp[tid * 2]     = __half2{l[0], l[1]};
    lp[tid * 2 + 1] = __half2{l[2], l[3]};
}

// ---------------- swiglu: planes = split(gate * up_raw) ----------------
__global__ void swiglu_split_kernel(const float* __restrict__ gate,
                                    const float* __restrict__ upraw,
                                    __half* __restrict__ hi,
                                    __half* __restrict__ lo) {
    int idx = blockIdx.x * 256 + threadIdx.x;   // float4 index
    float4 g = ((const float4*)gate)[idx];
    float4 u = ((const float4*)upraw)[idx];
    float vv[4] = {g.x * u.x, g.y * u.y, g.z * u.z, g.w * u.w};
    __half h[4], l[4];
#pragma unroll
    for (int j = 0; j < 4; j++) hsplit(vv[j], h[j], l[j]);
    __half2* hp = (__half2*)hi;
    __half2* lp = (__half2*)lo;
    hp[idx * 2]     = __half2{h[0], h[1]};
    hp[idx * 2 + 1] = __half2{h[2], h[3]};
    lp[idx * 2]     = __half2{l[0], l[1]};
    lp[idx * 2 + 1] = __half2{l[2], l[3]};
}

// ---------------- shared tile constants ----------------
#define BK 32
#define SP 40                 // f16 per smem row (32 data + 8 pad)
#define SP32 20               // in b32 units
#define PLANE (128 * SP)      // 5120 f16 = 10240 B
#define SM_G2 (2 * 3 * PLANE * 2)   // 61440 B
#define SM_G3 (2 * 4 * PLANE * 2)   // 81920 B
#define SM_G1 (2 * 2 * PLANE * 2)   // 40960 B

// ======== gemm2 core: C = (Ahi+Alo) * W^T  (2 MMAs/k16), KT iterations ========
// EPI: 0 store, 2 SiLU
template <int EPI>
__device__ __forceinline__ void gemm2_core(
    __half* smb,
    const __half* __restrict__ Ahi, const __half* __restrict__ Alo,
    const __half* __restrict__ W,
    float* __restrict__ C,
    int K, int M, int n0, int m0, int KT) {
    int tid = threadIdx.x, lane = tid & 31, warp = tid >> 5;
    int wm = warp >> 2, wn = warp & 3;

    const __half* Ah = Ahi + (size_t)n0 * K;
    const __half* Al = Alo + (size_t)n0 * K;
    const __half* Wg = W + (size_t)m0 * K;

    float acc[4][4][4] = {};

    auto load_stage = [&](int s, int kt) {
        __half* base = smb + s * (3 * PLANE);
        const __half* gp0 = Ah + kt;
        const __half* gp1 = Al + kt;
        const __half* gp2 = Wg + kt;
#pragma unroll
        for (int hf = 0; hf < 2; hf++) {
            int row = hf * 64 + (tid >> 2);
            int seg = tid & 3;
            cpa16((uint32_t)__cvta_generic_to_shared(base + row * SP + seg * 8),
                  gp0 + (size_t)row * K + seg * 8);
            cpa16((uint32_t)__cvta_generic_to_shared(base + PLANE + row * SP + seg * 8),
                  gp1 + (size_t)row * K + seg * 8);
            cpa16((uint32_t)__cvta_generic_to_shared(base + 2 * PLANE + row * SP + seg * 8),
                  gp2 + (size_t)row * K + seg * 8);
        }
        asm volatile("cp.async.commit_group;" ::: "memory");
    };

    load_stage(0, 0);
    int r = lane >> 2, c = lane & 3;
    for (int kt = 0; kt < KT; kt++) {
        asm volatile("cp.async.wait_group 0;" ::: "memory");
        __syncthreads();
        if (kt + 1 < KT) load_stage((kt + 1) & 1, (kt + 1) * BK);
        const __half* cb = smb + (kt & 1) * (3 * PLANE);
        const uint32_t* aH = (const uint32_t*)(cb);
        const uint32_t* aL = (const uint32_t*)(cb + PLANE);
        const uint32_t* wP = (const uint32_t*)(cb + 2 * PLANE);
#pragma unroll
        for (int ks = 0; ks < 2; ks++) {
            int kb = ks * 8 + c;
            uint32_t ah[4][4], al[4][4], b[4][2];
#pragma unroll
            for (int i = 0; i < 4; i++) {
                int m = wm * 64 + i * 16 + r;
                ah[i][0] = aH[m * SP32 + kb];
                ah[i][1] = aH[(m + 8) * SP32 + kb];
                ah[i][2] = aH[m * SP32 + kb + 4];
                ah[i][3] = aH[(m + 8) * SP32 + kb + 4];
                al[i][0] = aL[m * SP32 + kb];
                al[i][1] = aL[(m + 8) * SP32 + kb];
                al[i][2] = aL[m * SP32 + kb + 4];
                al[i][3] = aL[(m + 8) * SP32 + kb + 4];
            }
#pragma unroll
            for (int j = 0; j < 4; j++) {
                int n = wn * 32 + j * 8 + r;
                b[j][0] = wP[n * SP32 + kb];
                b[j][1] = wP[n * SP32 + kb + 4];
            }
#pragma unroll
            for (int i = 0; i < 4; i++)
#pragma unroll
                for (int j = 0; j < 4; j++) {
                    mma_f16(acc[i][j], ah[i], b[j]);
                    mma_f16(acc[i][j], al[i], b[j]);
                }
        }
        __syncthreads();
    }

    int rr = lane >> 2, cc = (lane & 3) * 2;
#pragma unroll
    for (int i = 0; i < 4; i++) {
#pragma unroll
        for (int half = 0; half < 2; half++) {
            int grow = n0 + wm * 64 + i * 16 + rr + half * 8;
#pragma unroll
            for (int j = 0; j < 4; j++) {
                int gcol = m0 + wn * 32 + j * 8 + cc;
                size_t off = (size_t)grow * M + gcol;
                float2 v = make_float2(acc[i][j][half * 2], acc[i][j][half * 2 + 1]);
                if (EPI == 2) {
                    v.x = v.x / (1.0f + __expf(-v.x));
                    v.y = v.y / (1.0f + __expf(-v.y));
                }
                *(float2*)(C + off) = v;
            }
        }
    }
}

// split-K=2 partial GEMM (w2): grid (TB, M/128, 2)
__global__ __launch_bounds__(256) void gemm2p_k(
    const __half* __restrict__ Ahi, const __half* __restrict__ Alo,
    const __half* __restrict__ W,
    float* __restrict__ P0, float* __restrict__ P1,
    int K, int M) {
    extern __shared__ __half smb[];
    int kz = blockIdx.z;
    int koff = kz * (K >> 1);
    float* C = kz ? P1 : P0;
    gemm2_core<0>(smb, Ahi + koff, Alo + koff, W + koff, C,
                  K, M, blockIdx.x * 128, blockIdx.y * 128, K >> 6);
}

// Fused QKV: grid (16, 12): y<8 -> Q, y in {8,9} -> K, y in {10,11} -> V
__global__ __launch_bounds__(256) void gemm_qkv(
    const __half* __restrict__ Ahi, const __half* __restrict__ Alo,
    const __half* __restrict__ Qw, const __half* __restrict__ Kw,
    const __half* __restrict__ Vw,
    float* __restrict__ Cq, float* __restrict__ Ck, float* __restrict__ Cv) {
    extern __shared__ __half smb[];
    int y = blockIdx.y;
    const __half* w;
    float* C;
    int m0, M;
    if (y < 8)       { w = Qw; C = Cq; m0 = y * 128;        M = DMODEL; }
    else if (y < 10) { w = Kw; C = Ck; m0 = (y - 8) * 128;  M = KVDIM; }
    else             { w = Vw; C = Cv; m0 = (y - 10) * 128; M = KVDIM; }
    gemm2_core<0>(smb, Ahi, Alo, w, C, DMODEL, M, blockIdx.x * 128, m0, DMODEL >> 5);
}

// Fused FFN up: grid (16, 64): y<32 -> w1 (SiLU -> gate), y>=32 -> w3 (raw -> upraw)
__global__ __launch_bounds__(256) void gemm_ffn(
    const __half* __restrict__ Ahi, const __half* __restrict__ Alo,
    const __half* __restrict__ W1, const __half* __restrict__ W3,
    float* __restrict__ Gate, float* __restrict__ Upraw) {
    extern __shared__ __half smb[];
    int y = blockIdx.y;
    if (y < 32) {
        gemm2_core<2>(smb, Ahi, Alo, W1, Gate, DMODEL, FFN,
                      blockIdx.x * 128, y * 128, DMODEL >> 5);
    } else {
        gemm2_core<0>(smb, Ahi, Alo, W3, Upraw, DMODEL, FFN,
                      blockIdx.x * 128, (y - 32) * 128, DMODEL >> 5);
    }
}

// ======== gemm3p: partial (Ahi+Alo)*Whi + Ahi*Wlo (o_proj, split-K=2) ========
__global__ __launch_bounds__(256) void gemm3p_k(
    const __half* __restrict__ Ahi, const __half* __restrict__ Alo,
    const __half* __restrict__ Whi, const __half* __restrict__ Wlo,
    float* __restrict__ P0, float* __restrict__ P1,
    int K, int M) {
    extern __shared__ __half smb[];
    int tid = threadIdx.x, lane = tid & 31, warp = tid >> 5;
    int wm = warp >> 2, wn = warp & 3;
    int n0 = blockIdx.x * 128, m0 = blockIdx.y * 128;
    int kz = blockIdx.z;
    int koff = kz * (K >> 1);
    float* C = kz ? P1 : P0;

    const __half* Ah = Ahi + koff + (size_t)n0 * K;
    const __half* Al = Alo + koff + (size_t)n0 * K;
    const __half* Wh = Whi + koff + (size_t)m0 * K;
    const __half* Wl = Wlo + koff + (size_t)m0 * K;

    float acc[4][4][4] = {};

    auto load_stage = [&](int s, int kt) {
        __half* base = smb + s * (4 * PLANE);
        const __half* gp0 = Ah + kt;
        const __half* gp1 = Al + kt;
        const __half* gp2 = Wh + kt;
        const __half* gp3 = Wl + kt;
#pragma unroll
        for (int hf = 0; hf < 2; hf++) {
            int row = hf * 64 + (tid >> 2);
            int seg = tid & 3;
            cpa16((uint32_t)__cvta_generic_to_shared(base + row * SP + seg * 8),
                  gp0 + (size_t)row * K + seg * 8);
            cpa16((uint32_t)__cvta_generic_to_shared(base + PLANE + row * SP + seg * 8),
                  gp1 + (size_t)row * K + seg * 8);
            cpa16((uint32_t)__cvta_generic_to_shared(base + 2 * PLANE + row * SP + seg * 8),
                  gp2 + (size_t)row * K + seg * 8);
            cpa16((uint32_t)__cvta_generic_to_shared(base + 3 * PLANE + row * SP + seg * 8),
                  gp3 + (size_t)row * K + seg * 8);
        }
        asm volatile("cp.async.commit_group;" ::: "memory");
    };

    load_stage(0, 0);
    int KT = K >> 6;
    int r = lane >> 2, c = lane & 3;
    for (int kt = 0; kt < KT; kt++) {
        asm volatile("cp.async.wait_group 0;" ::: "memory");
        __syncthreads();
        if (kt + 1 < KT) load_stage((kt + 1) & 1, (kt + 1) * BK);
        const __half* cb = smb + (kt & 1) * (4 * PLANE);
        const uint32_t* aH = (const uint32_t*)(cb);
        const uint32_t* aL = (const uint32_t*)(cb + PLANE);
        const uint32_t* wH = (const uint32_t*)(cb + 2 * PLANE);
        const uint32_t* wL = (const uint32_t*)(cb + 3 * PLANE);
#pragma unroll
        for (int ks = 0; ks < 2; ks++) {
            int kb = ks * 8 + c;
            uint32_t ah[4][4], al[4][4], bh[4][2], bl[4][2];
#pragma unroll
            for (int i = 0; i < 4; i++) {
                int m = wm * 64 + i * 16 + r;
                ah[i][0] = aH[m * SP32 + kb];
                ah[i][1] = aH[(m + 8) * SP32 + kb];
                ah[i][2] = aH[m * SP32 + kb + 4];
                ah[i][3] = aH[(m + 8) * SP32 + kb + 4];
                al[i][0] = aL[m * SP32 + kb];
                al[i][1] = aL[(m + 8) * SP32 + kb];
                al[i][2] = aL[m * SP32 + kb + 4];
                al[i][3] = aL[(m + 8) * SP32 + kb + 4];
            }
#pragma unroll
            for (int j = 0; j < 4; j++) {
                int n = wn * 32 + j * 8 + r;
                bh[j][0] = wH[n * SP32 + kb];
                bh[j][1] = wH[n * SP32 + kb + 4];
                bl[j][0] = wL[n * SP32 + kb];
                bl[j][1] = wL[n * SP32 + kb + 4];
            }
#pragma unroll
            for (int i = 0; i < 4; i++)
#pragma unroll
                for (int j = 0; j < 4; j++) {
                    mma_f16(acc[i][j], ah[i], bh[j]);
                    mma_f16(acc[i][j], al[i], bh[j]);
                    mma_f16(acc[i][j], ah[i], bl[j]);
                }
        }
        __syncthreads();
    }

    int rr = lane >> 2, cc = (lane & 3) * 2;
#pragma unroll
    for (int i = 0; i < 4; i++) {
#pragma unroll
        for (int half = 0; half < 2; half++) {
            int grow = n0 + wm * 64 + i * 16 + rr + half * 8;
#pragma unroll
            for (int j = 0; j < 4; j++) {
                int gcol = m0 + wn * 32 + j * 8 + cc;
                size_t off = (size_t)grow * M + gcol;
                *(float2*)(C + off) =
                    make_float2(acc[i][j][half * 2], acc[i][j][half * 2 + 1]);
            }
        }
    }
}

// ======== gemm1: C = A * W^T, single plane each (logits) ========
__global__ __launch_bounds__(256) void gemm1_k(
    const __half* __restrict__ A, const __half* __restrict__ W,
    float* __restrict__ C, int K, int M) {
    extern __shared__ __half smb[];
    int tid = threadIdx.x, lane = tid & 31, warp = tid >> 5;
    int wm = warp >> 2, wn = warp & 3;
    int n0 = blockIdx.x * 128, m0 = blockIdx.y * 128;

    const __half* Ag = A + (size_t)n0 * K;
    const __half* Wg = W + (size_t)m0 * K;

    float acc[4][4][4] = {};

    auto load_stage = [&](int s, int kt) {
        __half* base = smb + s * (2 * PLANE);
        const __half* gp0 = Ag + kt;
        const __half* gp1 = Wg + kt;
#pragma unroll
        for (int hf = 0; hf < 2; hf++) {
            int row = hf * 64 + (tid >> 2);
            int seg = tid & 3;
            cpa16((uint32_t)__cvta_generic_to_shared(base + row * SP + seg * 8),
                  gp0 + (size_t)row * K + seg * 8);
            cpa16((uint32_t)__cvta_generic_to_shared(base + PLANE + row * SP + seg * 8),
                  gp1 + (size_t)row * K + seg * 8);
        }
        asm volatile("cp.async.commit_group;" ::: "memory");
    };

    load_stage(0, 0);
    int KT = K >> 5;
    int r = lane >> 2, c = lane & 3;
    for (int kt = 0; kt < KT; kt++) {
        asm volatile("cp.async.wait_group 0;" ::: "memory");
        __syncthreads();
        if (kt + 1 < KT) load_stage((kt + 1) & 1, (kt + 1) * BK);
        const __half* cb = smb + (kt & 1) * (2 * PLANE);
        const uint32_t* aP = (const uint32_t*)(cb);
        const uint32_t* wP = (const uint32_t*)(cb + PLANE);
#pragma unroll
        for (int ks = 0; ks < 2; ks++) {
            int kb = ks * 8 + c;
            uint32_t a[4][4], b[4][2];
#pragma unroll
            for (int i = 0; i < 4; i++) {
                int m = wm * 64 + i * 16 + r;
                a[i][0] = aP[m * SP32 + kb];
                a[i][1] = aP[(m + 8) * SP32 + kb];
                a[i][2] = aP[m * SP32 + kb + 4];
                a[i][3] = aP[(m + 8) * SP32 + kb + 4];
            }
#pragma unroll
            for (int j = 0; j < 4; j++) {
                int n = wn * 32 + j * 8 + r;
                b[j][0] = wP[n * SP32 + kb];
                b[j][1] = wP[n * SP32 + kb + 4];
            }
#pragma unroll
            for (int i = 0; i < 4; i++)
#pragma unroll
                for (int j = 0; j < 4; j++)
                    mma_f16(acc[i][j], a[i], b[j]);
        }
        __syncthreads();
    }

    int rr = lane >> 2, cc = (lane & 3) * 2;
#pragma unroll
    for (int i = 0; i < 4; i++) {
#pragma unroll
        for (int half = 0; half < 2; half++) {
            int grow = n0 + wm * 64 + i * 16 + rr + half * 8;
#pragma unroll
            for (int j = 0; j < 4; j++) {
                int gcol = m0 + wn * 32 + j * 8 + cc;
                size_t off = (size_t)grow * M + gcol;
                *(float2*)(C + off) =
                    make_float2(acc[i][j][half * 2], acc[i][j][half * 2 + 1]);
            }
        }
    }
}

// ---------------- causal flash attention (fp32, GQA, fused RoPE) -> f16 planes ----------------
__global__ __launch_bounds__(256) void attn_kernel(
    const float* __restrict__ Q, const float* __restrict__ K,
    const float* __restrict__ V,
    __half* __restrict__ Ohi, __half* __restrict__ Olo) {
    __shared__ float Qs[64][64];
    __shared__ float Ks[32][68];
    __shared__ float Vs[32][64];
    __shared__ float Ps[64][33];
    int bh = blockIdx.y;
    int b = bh >> 4;
    int h = bh & 15;
    int kvh = h >> 2;
    int q0 = blockIdx.x * 64;
    int tid = threadIdx.x;
    int lane = tid & 31, warp = tid >> 5;
    const float scale = 0.125f;

    const float* Qbase = Q + ((size_t)(b * SEQ + q0)) * DMODEL + h * HEADDIM;
    for (int i = tid; i < 64 * 8; i += 256) {
        int row = i >> 3, c4 = i & 7;
        int t = q0 + row;
        const float* qp = Qbase + (size_t)row * DMODEL;
        float4 x1 = *(const float4*)(qp + c4 * 4);
        float4 x2 = *(const float4*)(qp + c4 * 4 + 32);
        float4 o1, o2;
        float* x1p = &x1.x; float* x2p = &x2.x;
        float* o1p = &o1.x; float* o2p = &o2.x;
#pragma unroll
        for (int j = 0; j < 4; j++) {
            int d = c4 * 4 + j;
            float inv = 1.0f / powf(10000.0f, (float)d * (1.0f / 32.0f));
            float s, c;
            sincosf((float)t * inv, &s, &c);
            o1p[j] = (x1p[j] * c - x2p[j] * s) * scale;
            o2p[j] = (x2p[j] * c + x1p[j] * s) * scale;
        }
        *(float4*)&Qs[row][c4 * 4] = o1;
        *(float4*)&Qs[row][c4 * 4 + 32] = o2;
    }

    float m[8], l[8], acc0[8], acc1[8];
#pragma unroll
    for (int r = 0; r < 8; r++) { m[r] = -1e30f; l[r] = 0.f; acc0[r] = 0.f; acc1[r] = 0.f; }

    int kend = q0 + 64;
    for (int kc = 0; kc < kend; kc += 32) {
        __syncthreads();
        const float* Kbase = K + ((size_t)(b * SEQ + kc)) * KVDIM + kvh * HEADDIM;
        const float* Vbase = V + ((size_t)(b * SEQ + kc)) * KVDIM + kvh * HEADDIM;
        for (int i = tid; i < 32 * 8; i += 256) {
            int row = i >> 3, c4 = i & 7;
            int t = kc + row;
            const float* kp = Kbase + (size_t)row * KVDIM;
            float4 x1 = *(const float4*)(kp + c4 * 4);
            float4 x2 = *(const float4*)(kp + c4 * 4 + 32);
            float4 o1, o2;
            float* x1p = &x1.x; float* x2p = &x2.x;
            float* o1p = &o1.x; float* o2p = &o2.x;
#pragma unroll
            for (int j = 0; j < 4; j++) {
                int d = c4 * 4 + j;
                float inv = 1.0f / powf(10000.0f, (float)d * (1.0f / 32.0f));
                float s, c;
                sincosf((float)t * inv, &s, &c);
                o1p[j] = x1p[j] * c - x2p[j] * s;
                o2p[j] = x2p[j] * c + x1p[j] * s;
            }
            *(float4*)&Ks[row][c4 * 4] = o1;
            *(float4*)&Ks[row][c4 * 4 + 32] = o2;
        }
        for (int i = tid; i < 32 * 16; i += 256) {
            int row = i >> 4, c = (i & 15) * 4;
            float4 vv = *(const float4*)(Vbase + (size_t)row * KVDIM + c);
            *(float4*)&Vs[row][c] = vv;
        }
        __syncthreads();

        float s[8] = {0.f, 0.f, 0.f, 0.f, 0.f, 0.f, 0.f, 0.f};
#pragma unroll
        for (int d4 = 0; d4 < 16; d4++) {
            float4 kv = *(const float4*)&Ks[lane][d4 * 4];
#pragma unroll
            for (int r = 0; r < 8; r++) {
                float4 qv = *(const float4*)&Qs[warp * 8 + r][d4 * 4];
                s[r] += qv.x * kv.x + qv.y * kv.y + qv.z * kv.z + qv.w * kv.w;
            }
        }
        int key = kc + lane;
#pragma unroll
        for (int r = 0; r < 8; r++) {
            int qrow = q0 + warp * 8 + r;
            float sv = (key <= qrow) ? s[r] : -1e30f;
            float mx = sv;
#pragma unroll
            for (int o = 16; o > 0; o >>= 1) mx = fmaxf(mx, __shfl_xor_sync(0xffffffffu, mx, o));
            float mn = fmaxf(m[r], mx);
            float p = __expf(sv - mn);
            float cor = __expf(m[r] - mn);
            float ps = p;
#pragma unroll
            for (int o = 16; o > 0; o >>= 1) ps += __shfl_xor_sync(0xffffffffu, ps, o);
            l[r] = l[r] * cor + ps;
            acc0[r] *= cor;
            acc1[r] *= cor;
            m[r] = mn;
            Ps[warp * 8 + r][lane] = p;
        }
        __syncwarp();
#pragma unroll 4
        for (int j = 0; j < 32; j++) {
            float v0 = Vs[j][lane];
            float v1 = Vs[j][lane + 32];
#pragma unroll
            for (int r = 0; r < 8; r++) {
                float p = Ps[warp * 8 + r][j];
                acc0[r] += p * v0;
                acc1[r] += p * v1;
            }
        }
    }

    size_t obase = ((size_t)(b * SEQ + q0)) * DMODEL + h * HEADDIM;
#pragma unroll
    for (int r = 0; r < 8; r++) {
        int row = warp * 8 + r;
        float inv = 1.0f / l[r];
        float v0 = acc0[r] * inv, v1 = acc1[r] * inv;
        __half h0, h1, l0, l1;
        hsplit(v0, h0, l0);
        hsplit(v1, h1, l1);
        size_t o0 = obase + (size_t)row * DMODEL + lane;
        Ohi[o0] = h0;  Olo[o0] = l0;
        Ohi[o0 + 32] = h1;  Olo[o0 + 32] = l1;
    }
}

// ---------------- host orchestration ----------------
extern "C" void kernel_launch(void* const* d_in, const int* in_sizes, int n_in,
                              void* d_out, int out_size) {
    const int*   ids = (const int*)d_in[0];
    const float* emb = (const float*)d_in[1];
    const float* ln1 = (const float*)d_in[2];
    const float* qw  = (const float*)d_in[3];
    const float* kw  = (const float*)d_in[4];
    const float* vw  = (const float*)d_in[5];
    const float* ow  = (const float*)d_in[6];
    const float* ln2 = (const float*)d_in[7];
    const float* w1  = (const float*)d_in[8];
    const float* w2  = (const float*)d_in[9];
    const float* w3  = (const float*)d_in[10];
    const float* lnf = (const float*)d_in[11];
    float* out = (float*)d_out;

    float *x, *q, *k, *v, *gate, *upraw, *p0, *p1;
    __half *hh, *hl, *oh, *ol, *uph, *upl;
    __half *embw, *qww, *kww, *vww, *owh, *owl, *w1w, *w2w, *w3w;
    cudaGetSymbolAddress((void**)&x, g_x);
    cudaGetSymbolAddress((void**)&q, g_q);
    cudaGetSymbolAddress((void**)&k, g_k);
    cudaGetSymbolAddress((void**)&v, g_v);
    cudaGetSymbolAddress((void**)&gate, g_gate);
    cudaGetSymbolAddress((void**)&upraw, g_upraw);
    cudaGetSymbolAddress((void**)&p0, g_p0);
    cudaGetSymbolAddress((void**)&p1, g_p1);
    cudaGetSymbolAddress((void**)&hh, g_h_h);
    cudaGetSymbolAddress((void**)&hl, g_h_l);
    cudaGetSymbolAddress((void**)&oh, g_o_h);
    cudaGetSymbolAddress((void**)&ol, g_o_l);
    cudaGetSymbolAddress((void**)&uph, g_up_h);
    cudaGetSymbolAddress((void**)&upl, g_up_l);
    cudaGetSymbolAddress((void**)&embw, s_emb_w);
    cudaGetSymbolAddress((void**)&qww, s_qw_w);
    cudaGetSymbolAddress((void**)&kww, s_kw_w);
    cudaGetSymbolAddress((void**)&vww, s_vw_w);
    cudaGetSymbolAddress((void**)&owh, s_ow_h);
    cudaGetSymbolAddress((void**)&owl, s_ow_l);
    cudaGetSymbolAddress((void**)&w1w, s_w1_w);
    cudaGetSymbolAddress((void**)&w2w, s_w2_w);
    cudaGetSymbolAddress((void**)&w3w, s_w3_w);

    cudaFuncSetAttribute(gemm2p_k,   cudaFuncAttributeMaxDynamicSharedMemorySize, SM_G2);
    cudaFuncSetAttribute(gemm3p_k,   cudaFuncAttributeMaxDynamicSharedMemorySize, SM_G3);
    cudaFuncSetAttribute(gemm1_k,    cudaFuncAttributeMaxDynamicSharedMemorySize, SM_G1);
    cudaFuncSetAttribute(gemm_qkv,   cudaFuncAttributeMaxDynamicSharedMemorySize, SM_G2);
    cudaFuncSetAttribute(gemm_ffn,   cudaFuncAttributeMaxDynamicSharedMemorySize, SM_G2);

    // pre-pass: weights -> f16 planes
    split_w_kernel<<<EMB_N / 1024, 256>>>(emb, embw);
    split_w_kernel<<<QW_N / 1024, 256>>>(qw, qww);
    split_w_kernel<<<KW_N / 1024, 256>>>(kw, kww);
    split_w_kernel<<<KW_N / 1024, 256>>>(vw, vww);
    split_w2_kernel<<<QW_N / 1024, 256>>>(ow, owh, owl);
    split_w_kernel<<<W1_N / 1024, 256>>>(w1, w1w);
    split_w_kernel<<<W1_N / 1024, 256>>>(w2, w2w);
    split_w_kernel<<<W1_N / 1024, 256>>>(w3, w3w);

    embed_kernel<<<NTOK, 256>>>(ids, emb, x);

    const int TB = NTOK / 128;   // 16 token blocks: FAST grid dim (weight L2 reuse)
    for (int l = 0; l < NLAYER; l++) {
        size_t qo = (size_t)l * DMODEL * DMODEL;
        size_t ko = (size_t)l * KVDIM * DMODEL;
        size_t fo = (size_t)l * FFN * DMODEL;

        // ln1: merge previous layer's w2 partials (layer 0: plain)
        if (l == 0)
            rmsnorm_split_kernel<<<NTOK, 256>>>(x, ln1, hh, hl);
        else
            rmsnorm_merge_split_kernel<<<NTOK, 256>>>(x, p0, p1,
                                                      ln1 + l * DMODEL, hh, hl);
        gemm_qkv<<<dim3(TB, 12), 256, SM_G2>>>(
            hh, hl, qww + qo, kww + ko, vww + ko, q, k, v);
        attn_kernel<<<dim3(SEQ / 64, 2 * NHEAD), 256>>>(q, k, v, oh, ol);
        // o_proj: split-K=2 partials
        gemm3p_k<<<dim3(TB, DMODEL / 128, 2), 256, SM_G3>>>(
            oh, ol, owh + qo, owl + qo, p0, p1, DMODEL, DMODEL);
        // ln2: merge o_proj partials into x
        rmsnorm_merge_split_kernel<<<NTOK, 256>>>(x, p0, p1,
                                                  ln2 + l * DMODEL, hh, hl);
        // w1 + w3 in one launch (independent halves of grid)
        gemm_ffn<<<dim3(TB, 64), 256, SM_G2>>>(
            hh, hl, w1w + fo, w3w + fo, gate, upraw);
        // planes = split(gate * upraw)
        swiglu_split_kernel<<<NTOK * FFN / 1024, 256>>>(gate, upraw, uph, upl);
        // w2: split-K=2 partials (merged at next ln1 or lnf)
        gemm2p_k<<<dim3(TB, DMODEL / 128, 2), 256, SM_G2>>>(
            uph, upl, w2w + fo, p0, p1, FFN, DMODEL);
    }

    // lnf: merge last layer's w2 partials
    rmsnorm_merge_split_kernel<<<NTOK, 256>>>(x, p0, p1, lnf, hh, hl);
    gemm1_k<<<dim3(TB, VOCAB / 128), 256, SM_G1>>>(hh, embw, out, DMODEL, VOCAB);
}

// round 16
// speedup vs baseline: 1.2901x; 1.2901x over previous
#include <cuda_runtime.h>
#include <cuda_bf16.h>
#include <cuda_fp16.h>
#include <stdint.h>
#include <math.h>

#define NTOK 2048
#define DMODEL 1024
#define NHEAD 16
#define NKV 4
#define HEADDIM 64
#define FFN 4096
#define VOCAB 32000
#define NLAYER 4
#define SEQ 1024
#define KVDIM (NKV * HEADDIM)   // 256

#define EMB_N (VOCAB * DMODEL)
#define QW_N (NLAYER * DMODEL * DMODEL)
#define KW_N (NLAYER * KVDIM * DMODEL)
#define W1_N (NLAYER * FFN * DMODEL)

// ---------------- scratch (device globals; no runtime allocation) ----------------
__device__ float g_x[NTOK * DMODEL];
__device__ float g_q[NTOK * DMODEL];
__device__ float g_k[NTOK * KVDIM];
__device__ float g_v[NTOK * KVDIM];
__device__ float g_gate[NTOK * FFN];
__device__ float g_p0[NTOK * DMODEL];
__device__ float g_p1[NTOK * DMODEL];
__device__ float g_rc[SEQ * 32];
__device__ float g_rs[SEQ * 32];

__device__ __half g_h_h[NTOK * DMODEL], g_h_l[NTOK * DMODEL];
__device__ __half g_o_h[NTOK * DMODEL], g_o_l[NTOK * DMODEL];
__device__ __half g_up_h[NTOK * FFN],  g_up_l[NTOK * FFN];

__device__ __half s_emb_w[EMB_N];
__device__ __half s_qw_w[QW_N];
__device__ __half s_kw_w[KW_N];
__device__ __half s_vw_w[KW_N];
__device__ __half s_ow_h[QW_N], s_ow_l[QW_N];
__device__ __half s_w1_w[W1_N];
__device__ __half s_w2_w[W1_N];
__device__ __half s_w3_w[W1_N];

// ---------------- helpers ----------------
__device__ __forceinline__ void cpa16(uint32_t s, const void* g) {
    asm volatile("cp.async.cg.shared.global [%0], [%1], 16;" :: "r"(s), "l"(g));
}
__device__ __forceinline__ void hsplit(float x, __half& h, __half& l) {
    h = __float2half_rn(x);
    l = __float2half_rn(x - __half2float(h));
}
__device__ __forceinline__ void mma_f16(float* d, const uint32_t* a, const uint32_t* b) {
    asm volatile(
        "mma.sync.aligned.m16n8k16.row.col.f32.f16.f16.f32 "
        "{%0,%1,%2,%3},{%4,%5,%6,%7},{%8,%9},{%0,%1,%2,%3};"
        : "+f"(d[0]), "+f"(d[1]), "+f"(d[2]), "+f"(d[3])
        : "r"(a[0]), "r"(a[1]), "r"(a[2]), "r"(a[3]), "r"(b[0]), "r"(b[1]));
}

// ---------------- pre-pass kernels ----------------
__global__ void split_w_kernel(const float* __restrict__ src,
                               __half* __restrict__ w) {
    int idx = blockIdx.x * 256 + threadIdx.x;   // float4 index
    float4 v = ((const float4*)src)[idx];
    __half2* wp = (__half2*)w;
    wp[idx * 2]     = __floats2half2_rn(v.x, v.y);
    wp[idx * 2 + 1] = __floats2half2_rn(v.z, v.w);
}
__global__ void split_w2_kernel(const float* __restrict__ src,
                                __half* __restrict__ hi,
                                __half* __restrict__ lo) {
    int idx = blockIdx.x * 256 + threadIdx.x;
    float4 v = ((const float4*)src)[idx];
    float vv[4] = {v.x, v.y, v.z, v.w};
    __half h[4], l[4];
#pragma unroll
    for (int j = 0; j < 4; j++) hsplit(vv[j], h[j], l[j]);
    __half2* hp = (__half2*)hi;
    __half2* lp = (__half2*)lo;
    hp[idx * 2]     = __half2{h[0], h[1]};
    hp[idx * 2 + 1] = __half2{h[2], h[3]};
    lp[idx * 2]     = __half2{l[0], l[1]};
    lp[idx * 2 + 1] = __half2{l[2], l[3]};
}
// RoPE cos/sin tables: [SEQ][32]
__global__ void rope_table_kernel(float* __restrict__ rc, float* __restrict__ rs) {
    int idx = blockIdx.x * 256 + threadIdx.x;   // t*32 + d
    int t = idx >> 5;
    int d = idx & 31;
    float inv = 1.0f / powf(10000.0f, (float)d * (1.0f / 32.0f));
    float s, c;
    sincosf((float)t * inv, &s, &c);
    rc[idx] = c;
    rs[idx] = s;
}

// ---------------- embedding gather ----------------
__global__ void embed_kernel(const int* __restrict__ ids,
                             const float* __restrict__ emb,
                             float* __restrict__ x) {
    int idx = blockIdx.x * 256 + threadIdx.x;
    int n = idx >> 8;
    int c = idx & 255;
    const float4* e4 = (const float4*)emb;
    ((float4*)x)[idx] = e4[(size_t)ids[n] * 256 + c];
}

// ---------------- RMSNorm -> f16 hi/lo planes ----------------
__global__ void rmsnorm_split_kernel(const float* __restrict__ x,
                                     const float* __restrict__ w,
                                     __half* __restrict__ hi,
                                     __half* __restrict__ lo) {
    int n = blockIdx.x;
    int tid = threadIdx.x;
    const float4* xr = (const float4*)(x + (size_t)n * DMODEL);
    float4 v = xr[tid];
    float ss = v.x * v.x + v.y * v.y + v.z * v.z + v.w * v.w;
#pragma unroll
    for (int o = 16; o > 0; o >>= 1) ss += __shfl_xor_sync(0xffffffffu, ss, o);
    __shared__ float red[8];
    if ((tid & 31) == 0) red[tid >> 5] = ss;
    __syncthreads();
    float tot = 0.f;
#pragma unroll
    for (int i = 0; i < 8; i++) tot += red[i];
    float r = rsqrtf(tot * (1.0f / DMODEL) + 1e-6f);
    float4 wv = ((const float4*)w)[tid];
    float ov[4] = {wv.x * v.x * r, wv.y * v.y * r, wv.z * v.z * r, wv.w * v.w * r};
    __half h[4], l[4];
#pragma unroll
    for (int j = 0; j < 4; j++) hsplit(ov[j], h[j], l[j]);
    __half2* hp = (__half2*)(hi + (size_t)n * DMODEL);
    __half2* lp = (__half2*)(lo + (size_t)n * DMODEL);
    hp[tid * 2]     = __half2{h[0], h[1]};
    hp[tid * 2 + 1] = __half2{h[2], h[3]};
    lp[tid * 2]     = __half2{l[0], l[1]};
    lp[tid * 2 + 1] = __half2{l[2], l[3]};
}

// ---------------- merge (x += P0 + P1) + RMSNorm -> f16 hi/lo planes ----------------
__global__ void rmsnorm_merge_split_kernel(float* __restrict__ x,
                                           const float* __restrict__ P0,
                                           const float* __restrict__ P1,
                                           const float* __restrict__ w,
                                           __half* __restrict__ hi,
                                           __half* __restrict__ lo) {
    int n = blockIdx.x;
    int tid = threadIdx.x;
    size_t base = (size_t)n * DMODEL;
    float4 v = ((const float4*)(x + base))[tid];
    float4 p0 = ((const float4*)(P0 + base))[tid];
    float4 p1 = ((const float4*)(P1 + base))[tid];
    v.x += p0.x + p1.x;
    v.y += p0.y + p1.y;
    v.z += p0.z + p1.z;
    v.w += p0.w + p1.w;
    ((float4*)(x + base))[tid] = v;
    float ss = v.x * v.x + v.y * v.y + v.z * v.z + v.w * v.w;
#pragma unroll
    for (int o = 16; o > 0; o >>= 1) ss += __shfl_xor_sync(0xffffffffu, ss, o);
    __shared__ float red[8];
    if ((tid & 31) == 0) red[tid >> 5] = ss;
    __syncthreads();
    float tot = 0.f;
#pragma unroll
    for (int i = 0; i < 8; i++) tot += red[i];
    float r = rsqrtf(tot * (1.0f / DMODEL) + 1e-6f);
    float4 wv = ((const float4*)w)[tid];
    float ov[4] = {wv.x * v.x * r, wv.y * v.y * r, wv.z * v.z * r, wv.w * v.w * r};
    __half h[4], l[4];
#pragma unroll
    for (int j = 0; j < 4; j++) hsplit(ov[j], h[j], l[j]);
    __half2* hp = (__half2*)(hi + base);
    __half2* lp = (__half2*)(lo + base);
    hp[tid * 2]     = __half2{h[0], h[1]};
    hp[tid * 2 + 1] = __half2{h[2], h[3]};
    lp[tid * 2]     = __half2{l[0], l[1]};
    lp[tid * 2 + 1] = __half2{l[2], l[3]};
}

// ---------------- shared tile constants ----------------
#define BK 32
#define SP 40                 // f16 per smem row (32 data + 8 pad)
#define SP32 20               // in b32 units
#define PLANE (128 * SP)      // 5120 f16 = 10240 B
#define SM_G2 (2 * 3 * PLANE * 2)   // 61440 B
#define SM_G3 (2 * 4 * PLANE * 2)   // 81920 B
#define SM_G1 (2 * 2 * PLANE * 2)   // 40960 B

// ======== gemm2 core: C = (Ahi+Alo) * W^T  (2 MMAs/k16), KT iterations ========
// EPI: 0 store, 2 SiLU, 3 (acc*aux) -> f16 hi/lo planes
template <int EPI>
__device__ __forceinline__ void gemm2_core(
    __half* smb,
    const __half* __restrict__ Ahi, const __half* __restrict__ Alo,
    const __half* __restrict__ W,
    float* __restrict__ C, const float* __restrict__ aux,
    __half* __restrict__ Phi, __half* __restrict__ Plo,
    int K, int M, int n0, int m0, int KT) {
    int tid = threadIdx.x, lane = tid & 31, warp = tid >> 5;
    int wm = warp >> 2, wn = warp & 3;

    const __half* Ah = Ahi + (size_t)n0 * K;
    const __half* Al = Alo + (size_t)n0 * K;
    const __half* Wg = W + (size_t)m0 * K;

    float acc[4][4][4] = {};

    auto load_stage = [&](int s, int kt) {
        __half* base = smb + s * (3 * PLANE);
        const __half* gp0 = Ah + kt;
        const __half* gp1 = Al + kt;
        const __half* gp2 = Wg + kt;
#pragma unroll
        for (int hf = 0; hf < 2; hf++) {
            int row = hf * 64 + (tid >> 2);
            int seg = tid & 3;
            cpa16((uint32_t)__cvta_generic_to_shared(base + row * SP + seg * 8),
                  gp0 + (size_t)row * K + seg * 8);
            cpa16((uint32_t)__cvta_generic_to_shared(base + PLANE + row * SP + seg * 8),
                  gp1 + (size_t)row * K + seg * 8);
            cpa16((uint32_t)__cvta_generic_to_shared(base + 2 * PLANE + row * SP + seg * 8),
                  gp2 + (size_t)row * K + seg * 8);
        }
        asm volatile("cp.async.commit_group;" ::: "memory");
    };

    load_stage(0, 0);
    int r = lane >> 2, c = lane & 3;
    for (int kt = 0; kt < KT; kt++) {
        asm volatile("cp.async.wait_group 0;" ::: "memory");
        __syncthreads();
        if (kt + 1 < KT) load_stage((kt + 1) & 1, (kt + 1) * BK);
        const __half* cb = smb + (kt & 1) * (3 * PLANE);
        const uint32_t* aH = (const uint32_t*)(cb);
        const uint32_t* aL = (const uint32_t*)(cb + PLANE);
        const uint32_t* wP = (const uint32_t*)(cb + 2 * PLANE);
#pragma unroll
        for (int ks = 0; ks < 2; ks++) {
            int kb = ks * 8 + c;
            uint32_t ah[4][4], al[4][4], b[4][2];
#pragma unroll
            for (int i = 0; i < 4; i++) {
                int m = wm * 64 + i * 16 + r;
                ah[i][0] = aH[m * SP32 + kb];
                ah[i][1] = aH[(m + 8) * SP32 + kb];
                ah[i][2] = aH[m * SP32 + kb + 4];
                ah[i][3] = aH[(m + 8) * SP32 + kb + 4];
                al[i][0] = aL[m * SP32 + kb];
                al[i][1] = aL[(m + 8) * SP32 + kb];
                al[i][2] = aL[m * SP32 + kb + 4];
                al[i][3] = aL[(m + 8) * SP32 + kb + 4];
            }
#pragma unroll
            for (int j = 0; j < 4; j++) {
                int n = wn * 32 + j * 8 + r;
                b[j][0] = wP[n * SP32 + kb];
                b[j][1] = wP[n * SP32 + kb + 4];
            }
#pragma unroll
            for (int i = 0; i < 4; i++)
#pragma unroll
                for (int j = 0; j < 4; j++) {
                    mma_f16(acc[i][j], ah[i], b[j]);
                    mma_f16(acc[i][j], al[i], b[j]);
                }
        }
        __syncthreads();
    }

    int rr = lane >> 2, cc = (lane & 3) * 2;
#pragma unroll
    for (int i = 0; i < 4; i++) {
#pragma unroll
        for (int half = 0; half < 2; half++) {
            int grow = n0 + wm * 64 + i * 16 + rr + half * 8;
#pragma unroll
            for (int j = 0; j < 4; j++) {
                int gcol = m0 + wn * 32 + j * 8 + cc;
                size_t off = (size_t)grow * M + gcol;
                float2 v = make_float2(acc[i][j][half * 2], acc[i][j][half * 2 + 1]);
                if (EPI == 2) {
                    v.x = v.x / (1.0f + __expf(-v.x));
                    v.y = v.y / (1.0f + __expf(-v.y));
                } else if (EPI == 3) {
                    float2 rv = *(const float2*)(aux + off);
                    v.x *= rv.x; v.y *= rv.y;
                    __half h0, h1, l0, l1;
                    hsplit(v.x, h0, l0);
                    hsplit(v.y, h1, l1);
                    *(__half2*)(Phi + off) = __half2{h0, h1};
                    *(__half2*)(Plo + off) = __half2{l0, l1};
                }
                if (EPI != 3) *(float2*)(C + off) = v;
            }
        }
    }
}

template <int EPI>
__global__ __launch_bounds__(256) void gemm2_k(
    const __half* __restrict__ Ahi, const __half* __restrict__ Alo,
    const __half* __restrict__ W,
    float* __restrict__ C, const float* __restrict__ aux,
    __half* __restrict__ Phi, __half* __restrict__ Plo,
    int K, int M) {
    extern __shared__ __half smb[];
    gemm2_core<EPI>(smb, Ahi, Alo, W, C, aux, Phi, Plo, K, M,
                    blockIdx.x * 128, blockIdx.y * 128, K >> 5);
}

// split-K=2 partial GEMM (w2): grid (TB, M/128, 2)
__global__ __launch_bounds__(256) void gemm2p_k(
    const __half* __restrict__ Ahi, const __half* __restrict__ Alo,
    const __half* __restrict__ W,
    float* __restrict__ P0, float* __restrict__ P1,
    int K, int M) {
    extern __shared__ __half smb[];
    int kz = blockIdx.z;
    int koff = kz * (K >> 1);
    float* C = kz ? P1 : P0;
    gemm2_core<0>(smb, Ahi + koff, Alo + koff, W + koff, C, nullptr, nullptr,
                  nullptr, K, M, blockIdx.x * 128, blockIdx.y * 128, K >> 6);
}

// Fused QKV: grid (16, 12): y<8 -> Q, y in {8,9} -> K, y in {10,11} -> V
__global__ __launch_bounds__(256) void gemm_qkv(
    const __half* __restrict__ Ahi, const __half* __restrict__ Alo,
    const __half* __restrict__ Qw, const __half* __restrict__ Kw,
    const __half* __restrict__ Vw,
    float* __restrict__ Cq, float* __restrict__ Ck, float* __restrict__ Cv) {
    extern __shared__ __half smb[];
    int y = blockIdx.y;
    const __half* w;
    float* C;
    int m0, M;
    if (y < 8)       { w = Qw; C = Cq; m0 = y * 128;        M = DMODEL; }
    else if (y < 10) { w = Kw; C = Ck; m0 = (y - 8) * 128;  M = KVDIM; }
    else             { w = Vw; C = Cv; m0 = (y - 10) * 128; M = KVDIM; }
    gemm2_core<0>(smb, Ahi, Alo, w, C, nullptr, nullptr, nullptr, DMODEL, M,
                  blockIdx.x * 128, m0, DMODEL >> 5);
}

// ======== gemm3p: partial (Ahi+Alo)*Whi + Ahi*Wlo (o_proj, split-K=2) ========
__global__ __launch_bounds__(256) void gemm3p_k(
    const __half* __restrict__ Ahi, const __half* __restrict__ Alo,
    const __half* __restrict__ Whi, const __half* __restrict__ Wlo,
    float* __restrict__ P0, float* __restrict__ P1,
    int K, int M) {
    extern __shared__ __half smb[];
    int tid = threadIdx.x, lane = tid & 31, warp = tid >> 5;
    int wm = warp >> 2, wn = warp & 3;
    int n0 = blockIdx.x * 128, m0 = blockIdx.y * 128;
    int kz = blockIdx.z;
    int koff = kz * (K >> 1);
    float* C = kz ? P1 : P0;

    const __half* Ah = Ahi + koff + (size_t)n0 * K;
    const __half* Al = Alo + koff + (size_t)n0 * K;
    const __half* Wh = Whi + koff + (size_t)m0 * K;
    const __half* Wl = Wlo + koff + (size_t)m0 * K;

    float acc[4][4][4] = {};

    auto load_stage = [&](int s, int kt) {
        __half* base = smb + s * (4 * PLANE);
        const __half* gp0 = Ah + kt;
        const __half* gp1 = Al + kt;
        const __half* gp2 = Wh + kt;
        const __half* gp3 = Wl + kt;
#pragma unroll
        for (int hf = 0; hf < 2; hf++) {
            int row = hf * 64 + (tid >> 2);
            int seg = tid & 3;
            cpa16((uint32_t)__cvta_generic_to_shared(base + row * SP + seg * 8),
                  gp0 + (size_t)row * K + seg * 8);
            cpa16((uint32_t)__cvta_generic_to_shared(base + PLANE + row * SP + seg * 8),
                  gp1 + (size_t)row * K + seg * 8);
            cpa16((uint32_t)__cvta_generic_to_shared(base + 2 * PLANE + row * SP + seg * 8),
                  gp2 + (size_t)row * K + seg * 8);
            cpa16((uint32_t)__cvta_generic_to_shared(base + 3 * PLANE + row * SP + seg * 8),
                  gp3 + (size_t)row * K + seg * 8);
        }
        asm volatile("cp.async.commit_group;" ::: "memory");
    };

    load_stage(0, 0);
    int KT = K >> 6;
    int r = lane >> 2, c = lane & 3;
    for (int kt = 0; kt < KT; kt++) {
        asm volatile("cp.async.wait_group 0;" ::: "memory");
        __syncthreads();
        if (kt + 1 < KT) load_stage((kt + 1) & 1, (kt + 1) * BK);
        const __half* cb = smb + (kt & 1) * (4 * PLANE);
        const uint32_t* aH = (const uint32_t*)(cb);
        const uint32_t* aL = (const uint32_t*)(cb + PLANE);
        const uint32_t* wH = (const uint32_t*)(cb + 2 * PLANE);
        const uint32_t* wL = (const uint32_t*)(cb + 3 * PLANE);
#pragma unroll
        for (int ks = 0; ks < 2; ks++) {
            int kb = ks * 8 + c;
            uint32_t ah[4][4], al[4][4], bh[4][2], bl[4][2];
#pragma unroll
            for (int i = 0; i < 4; i++) {
                int m = wm * 64 + i * 16 + r;
                ah[i][0] = aH[m * SP32 + kb];
                ah[i][1] = aH[(m + 8) * SP32 + kb];
                ah[i][2] = aH[m * SP32 + kb + 4];
                ah[i][3] = aH[(m + 8) * SP32 + kb + 4];
                al[i][0] = aL[m * SP32 + kb];
                al[i][1] = aL[(m + 8) * SP32 + kb];
                al[i][2] = aL[m * SP32 + kb + 4];
                al[i][3] = aL[(m + 8) * SP32 + kb + 4];
            }
#pragma unroll
            for (int j = 0; j < 4; j++) {
                int n = wn * 32 + j * 8 + r;
                bh[j][0] = wH[n * SP32 + kb];
                bh[j][1] = wH[n * SP32 + kb + 4];
                bl[j][0] = wL[n * SP32 + kb];
                bl[j][1] = wL[n * SP32 + kb + 4];
            }
#pragma unroll
            for (int i = 0; i < 4; i++)
#pragma unroll
                for (int j = 0; j < 4; j++) {
                    mma_f16(acc[i][j], ah[i], bh[j]);
                    mma_f16(acc[i][j], al[i], bh[j]);
                    mma_f16(acc[i][j], ah[i], bl[j]);
                }
        }
        __syncthreads();
    }

    int rr = lane >> 2, cc = (lane & 3) * 2;
#pragma unroll
    for (int i = 0; i < 4; i++) {
#pragma unroll
        for (int half = 0; half < 2; half++) {
            int grow = n0 + wm * 64 + i * 16 + rr + half * 8;
#pragma unroll
            for (int j = 0; j < 4; j++) {
                int gcol = m0 + wn * 32 + j * 8 + cc;
                size_t off = (size_t)grow * M + gcol;
                *(float2*)(C + off) =
                    make_float2(acc[i][j][half * 2], acc[i][j][half * 2 + 1]);
            }
        }
    }
}

// ======== gemm1: C = A * W^T, single plane each (logits) ========
__global__ __launch_bounds__(256) void gemm1_k(
    const __half* __restrict__ A, const __half* __restrict__ W,
    float* __restrict__ C, int K, int M) {
    extern __shared__ __half smb[];
    int tid = threadIdx.x, lane = tid & 31, warp = tid >> 5;
    int wm = warp >> 2, wn = warp & 3;
    int n0 = blockIdx.x * 128, m0 = blockIdx.y * 128;

    const __half* Ag = A + (size_t)n0 * K;
    const __half* Wg = W + (size_t)m0 * K;

    float acc[4][4][4] = {};

    auto load_stage = [&](int s, int kt) {
        __half* base = smb + s * (2 * PLANE);
        const __half* gp0 = Ag + kt;
        const __half* gp1 = Wg + kt;
#pragma unroll
        for (int hf = 0; hf < 2; hf++) {
            int row = hf * 64 + (tid >> 2);
            int seg = tid & 3;
            cpa16((uint32_t)__cvta_generic_to_shared(base + row * SP + seg * 8),
                  gp0 + (size_t)row * K + seg * 8);
            cpa16((uint32_t)__cvta_generic_to_shared(base + PLANE + row * SP + seg * 8),
                  gp1 + (size_t)row * K + seg * 8);
        }
        asm volatile("cp.async.commit_group;" ::: "memory");
    };

    load_stage(0, 0);
    int KT = K >> 5;
    int r = lane >> 2, c = lane & 3;
    for (int kt = 0; kt < KT; kt++) {
        asm volatile("cp.async.wait_group 0;" ::: "memory");
        __syncthreads();
        if (kt + 1 < KT) load_stage((kt + 1) & 1, (kt + 1) * BK);
        const __half* cb = smb + (kt & 1) * (2 * PLANE);
        const uint32_t* aP = (const uint32_t*)(cb);
        const uint32_t* wP = (const uint32_t*)(cb + PLANE);
#pragma unroll
        for (int ks = 0; ks < 2; ks++) {
            int kb = ks * 8 + c;
            uint32_t a[4][4], b[4][2];
#pragma unroll
            for (int i = 0; i < 4; i++) {
                int m = wm * 64 + i * 16 + r;
                a[i][0] = aP[m * SP32 + kb];
                a[i][1] = aP[(m + 8) * SP32 + kb];
                a[i][2] = aP[m * SP32 + kb + 4];
                a[i][3] = aP[(m + 8) * SP32 + kb + 4];
            }
#pragma unroll
            for (int j = 0; j < 4; j++) {
                int n = wn * 32 + j * 8 + r;
                b[j][0] = wP[n * SP32 + kb];
                b[j][1] = wP[n * SP32 + kb + 4];
            }
#pragma unroll
            for (int i = 0; i < 4; i++)
#pragma unroll
                for (int j = 0; j < 4; j++)
                    mma_f16(acc[i][j], a[i], b[j]);
        }
        __syncthreads();
    }

    int rr = lane >> 2, cc = (lane & 3) * 2;
#pragma unroll
    for (int i = 0; i < 4; i++) {
#pragma unroll
        for (int half = 0; half < 2; half++) {
            int grow = n0 + wm * 64 + i * 16 + rr + half * 8;
#pragma unroll
            for (int j = 0; j < 4; j++) {
                int gcol = m0 + wn * 32 + j * 8 + cc;
                size_t off = (size_t)grow * M + gcol;
                *(float2*)(C + off) =
                    make_float2(acc[i][j][half * 2], acc[i][j][half * 2 + 1]);
            }
        }
    }
}

// ---------------- causal flash attention (fp32, GQA, table RoPE) -> f16 planes ----------------
__global__ __launch_bounds__(256) void attn_kernel(
    const float* __restrict__ Q, const float* __restrict__ K,
    const float* __restrict__ V,
    __half* __restrict__ Ohi, __half* __restrict__ Olo) {
    __shared__ float Qs[64][64];
    __shared__ float Ks[32][68];
    __shared__ float Vs[32][64];
    __shared__ float Ps[64][33];
    int bh = blockIdx.y;
    int b = bh >> 4;
    int h = bh & 15;
    int kvh = h >> 2;
    int q0 = blockIdx.x * 64;
    int tid = threadIdx.x;
    int lane = tid & 31, warp = tid >> 5;
    const float scale = 0.125f;

    const float* Qbase = Q + ((size_t)(b * SEQ + q0)) * DMODEL + h * HEADDIM;
    for (int i = tid; i < 64 * 8; i += 256) {
        int row = i >> 3, c4 = i & 7;
        int t = q0 + row;
        const float* qp = Qbase + (size_t)row * DMODEL;
        float4 x1 = *(const float4*)(qp + c4 * 4);
        float4 x2 = *(const float4*)(qp + c4 * 4 + 32);
        float4 cv = *(const float4*)&g_rc[t * 32 + c4 * 4];
        float4 sv = *(const float4*)&g_rs[t * 32 + c4 * 4];
        float4 o1, o2;
        float* x1p = &x1.x; float* x2p = &x2.x;
        float* o1p = &o1.x; float* o2p = &o2.x;
        float* cp = &cv.x;  float* spp = &sv.x;
#pragma unroll
        for (int j = 0; j < 4; j++) {
            o1p[j] = (x1p[j] * cp[j] - x2p[j] * spp[j]) * scale;
            o2p[j] = (x2p[j] * cp[j] + x1p[j] * spp[j]) * scale;
        }
        *(float4*)&Qs[row][c4 * 4] = o1;
        *(float4*)&Qs[row][c4 * 4 + 32] = o2;
    }

    float m[8], l[8], acc0[8], acc1[8];
#pragma unroll
    for (int r = 0; r < 8; r++) { m[r] = -1e30f; l[r] = 0.f; acc0[r] = 0.f; acc1[r] = 0.f; }

    int kend = q0 + 64;
    for (int kc = 0; kc < kend; kc += 32) {
        __syncthreads();
        const float* Kbase = K + ((size_t)(b * SEQ + kc)) * KVDIM + kvh * HEADDIM;
        const float* Vbase = V + ((size_t)(b * SEQ + kc)) * KVDIM + kvh * HEADDIM;
        for (int i = tid; i < 32 * 8; i += 256) {
            int row = i >> 3, c4 = i & 7;
            int t = kc + row;
            const float* kp = Kbase + (size_t)row * KVDIM;
            float4 x1 = *(const float4*)(kp + c4 * 4);
            float4 x2 = *(const float4*)(kp + c4 * 4 + 32);
            float4 cv = *(const float4*)&g_rc[t * 32 + c4 * 4];
            float4 sv = *(const float4*)&g_rs[t * 32 + c4 * 4];
            float4 o1, o2;
            float* x1p = &x1.x; float* x2p = &x2.x;
            float* o1p = &o1.x; float* o2p = &o2.x;
            float* cp = &cv.x;  float* spp = &sv.x;
#pragma unroll
            for (int j = 0; j < 4; j++) {
                o1p[j] = x1p[j] * cp[j] - x2p[j] * spp[j];
                o2p[j] = x2p[j] * cp[j] + x1p[j] * spp[j];
            }
            *(float4*)&Ks[row][c4 * 4] = o1;
            *(float4*)&Ks[row][c4 * 4 + 32] = o2;
        }
        for (int i = tid; i < 32 * 16; i += 256) {
            int row = i >> 4, c = (i & 15) * 4;
            float4 vv = *(const float4*)(Vbase + (size_t)row * KVDIM + c);
            *(float4*)&Vs[row][c] = vv;
        }
        __syncthreads();

        float s[8] = {0.f, 0.f, 0.f, 0.f, 0.f, 0.f, 0.f, 0.f};
#pragma unroll
        for (int d4 = 0; d4 < 16; d4++) {
            float4 kv = *(const float4*)&Ks[lane][d4 * 4];
#pragma unroll
            for (int r = 0; r < 8; r++) {
                float4 qv = *(const float4*)&Qs[warp * 8 + r][d4 * 4];
                s[r] += qv.x * kv.x + qv.y * kv.y + qv.z * kv.z + qv.w * kv.w;
            }
        }
        int key = kc + lane;
#pragma unroll
        for (int r = 0; r < 8; r++) {
            int qrow = q0 + warp * 8 + r;
            float sv = (key <= qrow) ? s[r] : -1e30f;
            float mx = sv;
#pragma unroll
            for (int o = 16; o > 0; o >>= 1) mx = fmaxf(mx, __shfl_xor_sync(0xffffffffu, mx, o));
            float mn = fmaxf(m[r], mx);
            float p = __expf(sv - mn);
            float cor = __expf(m[r] - mn);
            float ps = p;
#pragma unroll
            for (int o = 16; o > 0; o >>= 1) ps += __shfl_xor_sync(0xffffffffu, ps, o);
            l[r] = l[r] * cor + ps;
            acc0[r] *= cor;
            acc1[r] *= cor;
            m[r] = mn;
            Ps[warp * 8 + r][lane] = p;
        }
        __syncwarp();
#pragma unroll 4
        for (int j = 0; j < 32; j++) {
            float v0 = Vs[j][lane];
            float v1 = Vs[j][lane + 32];
#pragma unroll
            for (int r = 0; r < 8; r++) {
                float p = Ps[warp * 8 + r][j];
                acc0[r] += p * v0;
                acc1[r] += p * v1;
            }
        }
    }

    size_t obase = ((size_t)(b * SEQ + q0)) * DMODEL + h * HEADDIM;
#pragma unroll
    for (int r = 0; r < 8; r++) {
        int row = warp * 8 + r;
        float inv = 1.0f / l[r];
        float v0 = acc0[r] * inv, v1 = acc1[r] * inv;
        __half h0, h1, l0, l1;
        hsplit(v0, h0, l0);
        hsplit(v1, h1, l1);
        size_t o0 = obase + (size_t)row * DMODEL + lane;
        Ohi[o0] = h0;  Olo[o0] = l0;
        Ohi[o0 + 32] = h1;  Olo[o0 + 32] = l1;
    }
}

// ---------------- host orchestration ----------------
extern "C" void kernel_launch(void* const* d_in, const int* in_sizes, int n_in,
                              void* d_out, int out_size) {
    const int*   ids = (const int*)d_in[0];
    const float* emb = (const float*)d_in[1];
    const float* ln1 = (const float*)d_in[2];
    const float* qw  = (const float*)d_in[3];
    const float* kw  = (const float*)d_in[4];
    const float* vw  = (const float*)d_in[5];
    const float* ow  = (const float*)d_in[6];
    const float* ln2 = (const float*)d_in[7];
    const float* w1  = (const float*)d_in[8];
    const float* w2  = (const float*)d_in[9];
    const float* w3  = (const float*)d_in[10];
    const float* lnf = (const float*)d_in[11];
    float* out = (float*)d_out;

    float *x, *q, *k, *v, *gate, *p0, *p1, *rc, *rs;
    __half *hh, *hl, *oh, *ol, *uph, *upl;
    __half *embw, *qww, *kww, *vww, *owh, *owl, *w1w, *w2w, *w3w;
    cudaGetSymbolAddress((void**)&x, g_x);
    cudaGetSymbolAddress((void**)&q, g_q);
    cudaGetSymbolAddress((void**)&k, g_k);
    cudaGetSymbolAddress((void**)&v, g_v);
    cudaGetSymbolAddress((void**)&gate, g_gate);
    cudaGetSymbolAddress((void**)&p0, g_p0);
    cudaGetSymbolAddress((void**)&p1, g_p1);
    cudaGetSymbolAddress((void**)&rc, g_rc);
    cudaGetSymbolAddress((void**)&rs, g_rs);
    cudaGetSymbolAddress((void**)&hh, g_h_h);
    cudaGetSymbolAddress((void**)&hl, g_h_l);
    cudaGetSymbolAddress((void**)&oh, g_o_h);
    cudaGetSymbolAddress((void**)&ol, g_o_l);
    cudaGetSymbolAddress((void**)&uph, g_up_h);
    cudaGetSymbolAddress((void**)&upl, g_up_l);
    cudaGetSymbolAddress((void**)&embw, s_emb_w);
    cudaGetSymbolAddress((void**)&qww, s_qw_w);
    cudaGetSymbolAddress((void**)&kww, s_kw_w);
    cudaGetSymbolAddress((void**)&vww, s_vw_w);
    cudaGetSymbolAddress((void**)&owh, s_ow_h);
    cudaGetSymbolAddress((void**)&owl, s_ow_l);
    cudaGetSymbolAddress((void**)&w1w, s_w1_w);
    cudaGetSymbolAddress((void**)&w2w, s_w2_w);
    cudaGetSymbolAddress((void**)&w3w, s_w3_w);

    cudaFuncSetAttribute(gemm2_k<0>, cudaFuncAttributeMaxDynamicSharedMemorySize, SM_G2);
    cudaFuncSetAttribute(gemm2_k<2>, cudaFuncAttributeMaxDynamicSharedMemorySize, SM_G2);
    cudaFuncSetAttribute(gemm2_k<3>, cudaFuncAttributeMaxDynamicSharedMemorySize, SM_G2);
    cudaFuncSetAttribute(gemm2p_k,   cudaFuncAttributeMaxDynamicSharedMemorySize, SM_G2);
    cudaFuncSetAttribute(gemm3p_k,   cudaFuncAttributeMaxDynamicSharedMemorySize, SM_G3);
    cudaFuncSetAttribute(gemm1_k,    cudaFuncAttributeMaxDynamicSharedMemorySize, SM_G1);
    cudaFuncSetAttribute(gemm_qkv,   cudaFuncAttributeMaxDynamicSharedMemorySize, SM_G2);

    // pre-pass: weights -> f16 planes, RoPE tables
    rope_table_kernel<<<SEQ * 32 / 256, 256>>>(rc, rs);
    split_w_kernel<<<EMB_N / 1024, 256>>>(emb, embw);
    split_w_kernel<<<QW_N / 1024, 256>>>(qw, qww);
    split_w_kernel<<<KW_N / 1024, 256>>>(kw, kww);
    split_w_kernel<<<KW_N / 1024, 256>>>(vw, vww);
    split_w2_kernel<<<QW_N / 1024, 256>>>(ow, owh, owl);
    split_w_kernel<<<W1_N / 1024, 256>>>(w1, w1w);
    split_w_kernel<<<W1_N / 1024, 256>>>(w2, w2w);
    split_w_kernel<<<W1_N / 1024, 256>>>(w3, w3w);

    embed_kernel<<<NTOK, 256>>>(ids, emb, x);

    const int TB = NTOK / 128;   // 16 token blocks: FAST grid dim (weight L2 reuse)
    for (int l = 0; l < NLAYER; l++) {
        size_t qo = (size_t)l * DMODEL * DMODEL;
        size_t ko = (size_t)l * KVDIM * DMODEL;
        size_t fo = (size_t)l * FFN * DMODEL;

        // ln1: merge previous layer's w2 partials (layer 0: plain)
        if (l == 0)
            rmsnorm_split_kernel<<<NTOK, 256>>>(x, ln1, hh, hl);
        else
            rmsnorm_merge_split_kernel<<<NTOK, 256>>>(x, p0, p1,
                                                      ln1 + l * DMODEL, hh, hl);
        gemm_qkv<<<dim3(TB, 12), 256, SM_G2>>>(
            hh, hl, qww + qo, kww + ko, vww + ko, q, k, v);
        attn_kernel<<<dim3(SEQ / 64, 2 * NHEAD), 256>>>(q, k, v, oh, ol);
        // o_proj: split-K=2 partials
        gemm3p_k<<<dim3(TB, DMODEL / 128, 2), 256, SM_G3>>>(
            oh, ol, owh + qo, owl + qo, p0, p1, DMODEL, DMODEL);
        // ln2: merge o_proj partials into x
        rmsnorm_merge_split_kernel<<<NTOK, 256>>>(x, p0, p1,
                                                  ln2 + l * DMODEL, hh, hl);
        gemm2_k<2><<<dim3(TB, FFN / 128), 256, SM_G2>>>(
            hh, hl, w1w + fo, gate, nullptr, nullptr, nullptr, DMODEL, FFN);
        gemm2_k<3><<<dim3(TB, FFN / 128), 256, SM_G2>>>(
            hh, hl, w3w + fo, nullptr, gate, uph, upl, DMODEL, FFN);
        // w2: split-K=2 partials (merged at next ln1 or lnf)
        gemm2p_k<<<dim3(TB, DMODEL / 128, 2), 256, SM_G2>>>(
            uph, upl, w2w + fo, p0, p1, FFN, DMODEL);
    }

    // lnf: merge last layer's w2 partials
    rmsnorm_merge_split_kernel<<<NTOK, 256>>>(x, p0, p1, lnf, hh, hl);
    gemm1_k<<<dim3(TB, VOCAB / 128), 256, SM_G1>>>(hh, embw, out, DMODEL, VOCAB);
}

// round 17
// speedup vs baseline: 1.3629x; 1.0565x over previous
#include <cuda_runtime.h>
#include <cuda_bf16.h>
#include <cuda_fp16.h>
#include <stdint.h>
#include <math.h>

#define NTOK 2048
#define DMODEL 1024
#define NHEAD 16
#define NKV 4
#define HEADDIM 64
#define FFN 4096
#define VOCAB 32000
#define NLAYER 4
#define SEQ 1024
#define KVDIM (NKV * HEADDIM)   // 256

#define EMB_N (VOCAB * DMODEL)
#define QW_N (NLAYER * DMODEL * DMODEL)
#define KW_N (NLAYER * KVDIM * DMODEL)
#define W1_N (NLAYER * FFN * DMODEL)

// ---------------- scratch (device globals; no runtime allocation) ----------------
__device__ float g_x[NTOK * DMODEL];
__device__ float g_q[NTOK * DMODEL];
__device__ float g_k[NTOK * KVDIM];
__device__ float g_v[NTOK * KVDIM];
__device__ float g_gate[NTOK * FFN];
__device__ float g_p0[NTOK * DMODEL];
__device__ float g_p1[NTOK * DMODEL];
__device__ float g_rc[SEQ * 32];
__device__ float g_rs[SEQ * 32];

__device__ __half g_h_h[NTOK * DMODEL], g_h_l[NTOK * DMODEL];
__device__ __half g_o_h[NTOK * DMODEL], g_o_l[NTOK * DMODEL];
__device__ __half g_up_h[NTOK * FFN],  g_up_l[NTOK * FFN];

__device__ __half s_emb_w[EMB_N];
__device__ __half s_qw_w[QW_N];
__device__ __half s_kw_w[KW_N];
__device__ __half s_vw_w[KW_N];
__device__ __half s_ow_h[QW_N], s_ow_l[QW_N];
__device__ __half s_w1_w[W1_N];
__device__ __half s_w2_w[W1_N];
__device__ __half s_w3_w[W1_N];

// ---------------- helpers ----------------
__device__ __forceinline__ void cpa16(uint32_t s, const void* g) {
    asm volatile("cp.async.cg.shared.global [%0], [%1], 16;" :: "r"(s), "l"(g));
}
__device__ __forceinline__ void hsplit(float x, __half& h, __half& l) {
    h = __float2half_rn(x);
    l = __float2half_rn(x - __half2float(h));
}
__device__ __forceinline__ void mma_f16(float* d, const uint32_t* a, const uint32_t* b) {
    asm volatile(
        "mma.sync.aligned.m16n8k16.row.col.f32.f16.f16.f32 "
        "{%0,%1,%2,%3},{%4,%5,%6,%7},{%8,%9},{%0,%1,%2,%3};"
        : "+f"(d[0]), "+f"(d[1]), "+f"(d[2]), "+f"(d[3])
        : "r"(a[0]), "r"(a[1]), "r"(a[2]), "r"(a[3]), "r"(b[0]), "r"(b[1]));
}

// ---------------- pre-pass kernels ----------------
__global__ void split_w_kernel(const float* __restrict__ src,
                               __half* __restrict__ w) {
    int idx = blockIdx.x * 256 + threadIdx.x;   // float4 index
    float4 v = ((const float4*)src)[idx];
    __half2* wp = (__half2*)w;
    wp[idx * 2]     = __floats2half2_rn(v.x, v.y);
    wp[idx * 2 + 1] = __floats2half2_rn(v.z, v.w);
}
__global__ void split_w2_kernel(const float* __restrict__ src,
                                __half* __restrict__ hi,
                                __half* __restrict__ lo) {
    int idx = blockIdx.x * 256 + threadIdx.x;
    float4 v = ((const float4*)src)[idx];
    float vv[4] = {v.x, v.y, v.z, v.w};
    __half h[4], l[4];
#pragma unroll
    for (int j = 0; j < 4; j++) hsplit(vv[j], h[j], l[j]);
    __half2* hp = (__half2*)hi;
    __half2* lp = (__half2*)lo;
    hp[idx * 2]     = __half2{h[0], h[1]};
    hp[idx * 2 + 1] = __half2{h[2], h[3]};
    lp[idx * 2]     = __half2{l[0], l[1]};
    lp[idx * 2 + 1] = __half2{l[2], l[3]};
}
// RoPE cos/sin tables: [SEQ][32]
__global__ void rope_table_kernel(float* __restrict__ rc, float* __restrict__ rs) {
    int idx = blockIdx.x * 256 + threadIdx.x;   // t*32 + d
    int t = idx >> 5;
    int d = idx & 31;
    float inv = 1.0f / powf(10000.0f, (float)d * (1.0f / 32.0f));
    float s, c;
    sincosf((float)t * inv, &s, &c);
    rc[idx] = c;
    rs[idx] = s;
}

// ---------------- embedding gather ----------------
__global__ void embed_kernel(const int* __restrict__ ids,
                             const float* __restrict__ emb,
                             float* __restrict__ x) {
    int idx = blockIdx.x * 256 + threadIdx.x;
    int n = idx >> 8;
    int c = idx & 255;
    const float4* e4 = (const float4*)emb;
    ((float4*)x)[idx] = e4[(size_t)ids[n] * 256 + c];
}

// ---------------- RMSNorm -> f16 hi/lo planes ----------------
__global__ void rmsnorm_split_kernel(const float* __restrict__ x,
                                     const float* __restrict__ w,
                                     __half* __restrict__ hi,
                                     __half* __restrict__ lo) {
    int n = blockIdx.x;
    int tid = threadIdx.x;
    const float4* xr = (const float4*)(x + (size_t)n * DMODEL);
    float4 v = xr[tid];
    float ss = v.x * v.x + v.y * v.y + v.z * v.z + v.w * v.w;
#pragma unroll
    for (int o = 16; o > 0; o >>= 1) ss += __shfl_xor_sync(0xffffffffu, ss, o);
    __shared__ float red[8];
    if ((tid & 31) == 0) red[tid >> 5] = ss;
    __syncthreads();
    float tot = 0.f;
#pragma unroll
    for (int i = 0; i < 8; i++) tot += red[i];
    float r = rsqrtf(tot * (1.0f / DMODEL) + 1e-6f);
    float4 wv = ((const float4*)w)[tid];
    float ov[4] = {wv.x * v.x * r, wv.y * v.y * r, wv.z * v.z * r, wv.w * v.w * r};
    __half h[4], l[4];
#pragma unroll
    for (int j = 0; j < 4; j++) hsplit(ov[j], h[j], l[j]);
    __half2* hp = (__half2*)(hi + (size_t)n * DMODEL);
    __half2* lp = (__half2*)(lo + (size_t)n * DMODEL);
    hp[tid * 2]     = __half2{h[0], h[1]};
    hp[tid * 2 + 1] = __half2{h[2], h[3]};
    lp[tid * 2]     = __half2{l[0], l[1]};
    lp[tid * 2 + 1] = __half2{l[2], l[3]};
}

// ---------------- merge (x += P0 + P1) + RMSNorm -> f16 hi/lo planes ----------------
__global__ void rmsnorm_merge_split_kernel(float* __restrict__ x,
                                           const float* __restrict__ P0,
                                           const float* __restrict__ P1,
                                           const float* __restrict__ w,
                                           __half* __restrict__ hi,
                                           __half* __restrict__ lo) {
    int n = blockIdx.x;
    int tid = threadIdx.x;
    size_t base = (size_t)n * DMODEL;
    float4 v = ((const float4*)(x + base))[tid];
    float4 p0 = ((const float4*)(P0 + base))[tid];
    float4 p1 = ((const float4*)(P1 + base))[tid];
    v.x += p0.x + p1.x;
    v.y += p0.y + p1.y;
    v.z += p0.z + p1.z;
    v.w += p0.w + p1.w;
    ((float4*)(x + base))[tid] = v;
    float ss = v.x * v.x + v.y * v.y + v.z * v.z + v.w * v.w;
#pragma unroll
    for (int o = 16; o > 0; o >>= 1) ss += __shfl_xor_sync(0xffffffffu, ss, o);
    __shared__ float red[8];
    if ((tid & 31) == 0) red[tid >> 5] = ss;
    __syncthreads();
    float tot = 0.f;
#pragma unroll
    for (int i = 0; i < 8; i++) tot += red[i];
    float r = rsqrtf(tot * (1.0f / DMODEL) + 1e-6f);
    float4 wv = ((const float4*)w)[tid];
    float ov[4] = {wv.x * v.x * r, wv.y * v.y * r, wv.z * v.z * r, wv.w * v.w * r};
    __half h[4], l[4];
#pragma unroll
    for (int j = 0; j < 4; j++) hsplit(ov[j], h[j], l[j]);
    __half2* hp = (__half2*)(hi + base);
    __half2* lp = (__half2*)(lo + base);
    hp[tid * 2]     = __half2{h[0], h[1]};
    hp[tid * 2 + 1] = __half2{h[2], h[3]};
    lp[tid * 2]     = __half2{l[0], l[1]};
    lp[tid * 2 + 1] = __half2{l[2], l[3]};
}

// ---------------- shared tile constants ----------------
#define BK 32
#define SP 40                 // f16 per smem row (32 data + 8 pad)
#define SP32 20               // in b32 units
#define PLANE (128 * SP)      // 5120 f16 = 10240 B
#define SM_G2 (2 * 3 * PLANE * 2)   // 61440 B
#define SM_G3 (2 * 4 * PLANE * 2)   // 81920 B
#define SM_G1 (2 * 2 * PLANE * 2)   // 40960 B

// ======== gemm2 core: C = (Ahi+Alo) * W^T  (2 MMAs/k16), KT iterations ========
// EPI: 0 store, 2 SiLU, 3 (acc*aux) -> f16 hi/lo planes
template <int EPI>
__device__ __forceinline__ void gemm2_core(
    __half* smb,
    const __half* __restrict__ Ahi, const __half* __restrict__ Alo,
    const __half* __restrict__ W,
    float* __restrict__ C, const float* __restrict__ aux,
    __half* __restrict__ Phi, __half* __restrict__ Plo,
    int K, int M, int n0, int m0, int KT) {
    int tid = threadIdx.x, lane = tid & 31, warp = tid >> 5;
    int wm = warp >> 2, wn = warp & 3;

    const __half* Ah = Ahi + (size_t)n0 * K;
    const __half* Al = Alo + (size_t)n0 * K;
    const __half* Wg = W + (size_t)m0 * K;

    float acc[4][4][4] = {};

    auto load_stage = [&](int s, int kt) {
        __half* base = smb + s * (3 * PLANE);
        const __half* gp0 = Ah + kt;
        const __half* gp1 = Al + kt;
        const __half* gp2 = Wg + kt;
#pragma unroll
        for (int hf = 0; hf < 2; hf++) {
            int row = hf * 64 + (tid >> 2);
            int seg = tid & 3;
            cpa16((uint32_t)__cvta_generic_to_shared(base + row * SP + seg * 8),
                  gp0 + (size_t)row * K + seg * 8);
            cpa16((uint32_t)__cvta_generic_to_shared(base + PLANE + row * SP + seg * 8),
                  gp1 + (size_t)row * K + seg * 8);
            cpa16((uint32_t)__cvta_generic_to_shared(base + 2 * PLANE + row * SP + seg * 8),
                  gp2 + (size_t)row * K + seg * 8);
        }
        asm volatile("cp.async.commit_group;" ::: "memory");
    };

    load_stage(0, 0);
    int r = lane >> 2, c = lane & 3;
    for (int kt = 0; kt < KT; kt++) {
        asm volatile("cp.async.wait_group 0;" ::: "memory");
        __syncthreads();
        if (kt + 1 < KT) load_stage((kt + 1) & 1, (kt + 1) * BK);
        const __half* cb = smb + (kt & 1) * (3 * PLANE);
        const uint32_t* aH = (const uint32_t*)(cb);
        const uint32_t* aL = (const uint32_t*)(cb + PLANE);
        const uint32_t* wP = (const uint32_t*)(cb + 2 * PLANE);
#pragma unroll
        for (int ks = 0; ks < 2; ks++) {
            int kb = ks * 8 + c;
            uint32_t ah[4][4], al[4][4], b[4][2];
#pragma unroll
            for (int i = 0; i < 4; i++) {
                int m = wm * 64 + i * 16 + r;
                ah[i][0] = aH[m * SP32 + kb];
                ah[i][1] = aH[(m + 8) * SP32 + kb];
                ah[i][2] = aH[m * SP32 + kb + 4];
                ah[i][3] = aH[(m + 8) * SP32 + kb + 4];
                al[i][0] = aL[m * SP32 + kb];
                al[i][1] = aL[(m + 8) * SP32 + kb];
                al[i][2] = aL[m * SP32 + kb + 4];
                al[i][3] = aL[(m + 8) * SP32 + kb + 4];
            }
#pragma unroll
            for (int j = 0; j < 4; j++) {
                int n = wn * 32 + j * 8 + r;
                b[j][0] = wP[n * SP32 + kb];
                b[j][1] = wP[n * SP32 + kb + 4];
            }
#pragma unroll
            for (int i = 0; i < 4; i++)
#pragma unroll
                for (int j = 0; j < 4; j++) {
                    mma_f16(acc[i][j], ah[i], b[j]);
                    mma_f16(acc[i][j], al[i], b[j]);
                }
        }
        __syncthreads();
    }

    int rr = lane >> 2, cc = (lane & 3) * 2;
#pragma unroll
    for (int i = 0; i < 4; i++) {
#pragma unroll
        for (int half = 0; half < 2; half++) {
            int grow = n0 + wm * 64 + i * 16 + rr + half * 8;
#pragma unroll
            for (int j = 0; j < 4; j++) {
                int gcol = m0 + wn * 32 + j * 8 + cc;
                size_t off = (size_t)grow * M + gcol;
                float2 v = make_float2(acc[i][j][half * 2], acc[i][j][half * 2 + 1]);
                if (EPI == 2) {
                    v.x = v.x / (1.0f + __expf(-v.x));
                    v.y = v.y / (1.0f + __expf(-v.y));
                } else if (EPI == 3) {
                    float2 rv = *(const float2*)(aux + off);
                    v.x *= rv.x; v.y *= rv.y;
                    __half h0, h1, l0, l1;
                    hsplit(v.x, h0, l0);
                    hsplit(v.y, h1, l1);
                    *(__half2*)(Phi + off) = __half2{h0, h1};
                    *(__half2*)(Plo + off) = __half2{l0, l1};
                }
                if (EPI != 3) *(float2*)(C + off) = v;
            }
        }
    }
}

template <int EPI>
__global__ __launch_bounds__(256) void gemm2_k(
    const __half* __restrict__ Ahi, const __half* __restrict__ Alo,
    const __half* __restrict__ W,
    float* __restrict__ C, const float* __restrict__ aux,
    __half* __restrict__ Phi, __half* __restrict__ Plo,
    int K, int M) {
    extern __shared__ __half smb[];
    gemm2_core<EPI>(smb, Ahi, Alo, W, C, aux, Phi, Plo, K, M,
                    blockIdx.x * 128, blockIdx.y * 128, K >> 5);
}

// split-K=2 partial GEMM (w2): grid (TB, M/128, 2)
__global__ __launch_bounds__(256) void gemm2p_k(
    const __half* __restrict__ Ahi, const __half* __restrict__ Alo,
    const __half* __restrict__ W,
    float* __restrict__ P0, float* __restrict__ P1,
    int K, int M) {
    extern __shared__ __half smb[];
    int kz = blockIdx.z;
    int koff = kz * (K >> 1);
    float* C = kz ? P1 : P0;
    gemm2_core<0>(smb, Ahi + koff, Alo + koff, W + koff, C, nullptr, nullptr,
                  nullptr, K, M, blockIdx.x * 128, blockIdx.y * 128, K >> 6);
}

// Fused QKV: grid (16, 12): y<8 -> Q, y in {8,9} -> K, y in {10,11} -> V
__global__ __launch_bounds__(256) void gemm_qkv(
    const __half* __restrict__ Ahi, const __half* __restrict__ Alo,
    const __half* __restrict__ Qw, const __half* __restrict__ Kw,
    const __half* __restrict__ Vw,
    float* __restrict__ Cq, float* __restrict__ Ck, float* __restrict__ Cv) {
    extern __shared__ __half smb[];
    int y = blockIdx.y;
    const __half* w;
    float* C;
    int m0, M;
    if (y < 8)       { w = Qw; C = Cq; m0 = y * 128;        M = DMODEL; }
    else if (y < 10) { w = Kw; C = Ck; m0 = (y - 8) * 128;  M = KVDIM; }
    else             { w = Vw; C = Cv; m0 = (y - 10) * 128; M = KVDIM; }
    gemm2_core<0>(smb, Ahi, Alo, w, C, nullptr, nullptr, nullptr, DMODEL, M,
                  blockIdx.x * 128, m0, DMODEL >> 5);
}

// ======== gemm3p: partial (Ahi+Alo)*Whi + Ahi*Wlo (o_proj, split-K=2) ========
__global__ __launch_bounds__(256) void gemm3p_k(
    const __half* __restrict__ Ahi, const __half* __restrict__ Alo,
    const __half* __restrict__ Whi, const __half* __restrict__ Wlo,
    float* __restrict__ P0, float* __restrict__ P1,
    int K, int M) {
    extern __shared__ __half smb[];
    int tid = threadIdx.x, lane = tid & 31, warp = tid >> 5;
    int wm = warp >> 2, wn = warp & 3;
    int n0 = blockIdx.x * 128, m0 = blockIdx.y * 128;
    int kz = blockIdx.z;
    int koff = kz * (K >> 1);
    float* C = kz ? P1 : P0;

    const __half* Ah = Ahi + koff + (size_t)n0 * K;
    const __half* Al = Alo + koff + (size_t)n0 * K;
    const __half* Wh = Whi + koff + (size_t)m0 * K;
    const __half* Wl = Wlo + koff + (size_t)m0 * K;

    float acc[4][4][4] = {};

    auto load_stage = [&](int s, int kt) {
        __half* base = smb + s * (4 * PLANE);
        const __half* gp0 = Ah + kt;
        const __half* gp1 = Al + kt;
        const __half* gp2 = Wh + kt;
        const __half* gp3 = Wl + kt;
#pragma unroll
        for (int hf = 0; hf < 2; hf++) {
            int row = hf * 64 + (tid >> 2);
            int seg = tid & 3;
            cpa16((uint32_t)__cvta_generic_to_shared(base + row * SP + seg * 8),
                  gp0 + (size_t)row * K + seg * 8);
            cpa16((uint32_t)__cvta_generic_to_shared(base + PLANE + row * SP + seg * 8),
                  gp1 + (size_t)row * K + seg * 8);
            cpa16((uint32_t)__cvta_generic_to_shared(base + 2 * PLANE + row * SP + seg * 8),
                  gp2 + (size_t)row * K + seg * 8);
            cpa16((uint32_t)__cvta_generic_to_shared(base + 3 * PLANE + row * SP + seg * 8),
                  gp3 + (size_t)row * K + seg * 8);
        }
        asm volatile("cp.async.commit_group;" ::: "memory");
    };

    load_stage(0, 0);
    int KT = K >> 6;
    int r = lane >> 2, c = lane & 3;
    for (int kt = 0; kt < KT; kt++) {
        asm volatile("cp.async.wait_group 0;" ::: "memory");
        __syncthreads();
        if (kt + 1 < KT) load_stage((kt + 1) & 1, (kt + 1) * BK);
        const __half* cb = smb + (kt & 1) * (4 * PLANE);
        const uint32_t* aH = (const uint32_t*)(cb);
        const uint32_t* aL = (const uint32_t*)(cb + PLANE);
        const uint32_t* wH = (const uint32_t*)(cb + 2 * PLANE);
        const uint32_t* wL = (const uint32_t*)(cb + 3 * PLANE);
#pragma unroll
        for (int ks = 0; ks < 2; ks++) {
            int kb = ks * 8 + c;
            uint32_t ah[4][4], al[4][4], bh[4][2], bl[4][2];
#pragma unroll
            for (int i = 0; i < 4; i++) {
                int m = wm * 64 + i * 16 + r;
                ah[i][0] = aH[m * SP32 + kb];
                ah[i][1] = aH[(m + 8) * SP32 + kb];
                ah[i][2] = aH[m * SP32 + kb + 4];
                ah[i][3] = aH[(m + 8) * SP32 + kb + 4];
                al[i][0] = aL[m * SP32 + kb];
                al[i][1] = aL[(m + 8) * SP32 + kb];
                al[i][2] = aL[m * SP32 + kb + 4];
                al[i][3] = aL[(m + 8) * SP32 + kb + 4];
            }
#pragma unroll
            for (int j = 0; j < 4; j++) {
                int n = wn * 32 + j * 8 + r;
                bh[j][0] = wH[n * SP32 + kb];
                bh[j][1] = wH[n * SP32 + kb + 4];
                bl[j][0] = wL[n * SP32 + kb];
                bl[j][1] = wL[n * SP32 + kb + 4];
            }
#pragma unroll
            for (int i = 0; i < 4; i++)
#pragma unroll
                for (int j = 0; j < 4; j++) {
                    mma_f16(acc[i][j], ah[i], bh[j]);
                    mma_f16(acc[i][j], al[i], bh[j]);
                    mma_f16(acc[i][j], ah[i], bl[j]);
                }
        }
        __syncthreads();
    }

    int rr = lane >> 2, cc = (lane & 3) * 2;
#pragma unroll
    for (int i = 0; i < 4; i++) {
#pragma unroll
        for (int half = 0; half < 2; half++) {
            int grow = n0 + wm * 64 + i * 16 + rr + half * 8;
#pragma unroll
            for (int j = 0; j < 4; j++) {
                int gcol = m0 + wn * 32 + j * 8 + cc;
                size_t off = (size_t)grow * M + gcol;
                *(float2*)(C + off) =
                    make_float2(acc[i][j][half * 2], acc[i][j][half * 2 + 1]);
            }
        }
    }
}

// ======== gemm1: C = A * W^T, single plane each (logits) ========
__global__ __launch_bounds__(256) void gemm1_k(
    const __half* __restrict__ A, const __half* __restrict__ W,
    float* __restrict__ C, int K, int M) {
    extern __shared__ __half smb[];
    int tid = threadIdx.x, lane = tid & 31, warp = tid >> 5;
    int wm = warp >> 2, wn = warp & 3;
    int n0 = blockIdx.x * 128, m0 = blockIdx.y * 128;

    const __half* Ag = A + (size_t)n0 * K;
    const __half* Wg = W + (size_t)m0 * K;

    float acc[4][4][4] = {};

    auto load_stage = [&](int s, int kt) {
        __half* base = smb + s * (2 * PLANE);
        const __half* gp0 = Ag + kt;
        const __half* gp1 = Wg + kt;
#pragma unroll
        for (int hf = 0; hf < 2; hf++) {
            int row = hf * 64 + (tid >> 2);
            int seg = tid & 3;
            cpa16((uint32_t)__cvta_generic_to_shared(base + row * SP + seg * 8),
                  gp0 + (size_t)row * K + seg * 8);
            cpa16((uint32_t)__cvta_generic_to_shared(base + PLANE + row * SP + seg * 8),
                  gp1 + (size_t)row * K + seg * 8);
        }
        asm volatile("cp.async.commit_group;" ::: "memory");
    };

    load_stage(0, 0);
    int KT = K >> 5;
    int r = lane >> 2, c = lane & 3;
    for (int kt = 0; kt < KT; kt++) {
        asm volatile("cp.async.wait_group 0;" ::: "memory");
        __syncthreads();
        if (kt + 1 < KT) load_stage((kt + 1) & 1, (kt + 1) * BK);
        const __half* cb = smb + (kt & 1) * (2 * PLANE);
        const uint32_t* aP = (const uint32_t*)(cb);
        const uint32_t* wP = (const uint32_t*)(cb + PLANE);
#pragma unroll
        for (int ks = 0; ks < 2; ks++) {
            int kb = ks * 8 + c;
            uint32_t a[4][4], b[4][2];
#pragma unroll
            for (int i = 0; i < 4; i++) {
                int m = wm * 64 + i * 16 + r;
                a[i][0] = aP[m * SP32 + kb];
                a[i][1] = aP[(m + 8) * SP32 + kb];
                a[i][2] = aP[m * SP32 + kb + 4];
                a[i][3] = aP[(m + 8) * SP32 + kb + 4];
            }
#pragma unroll
            for (int j = 0; j < 4; j++) {
                int n = wn * 32 + j * 8 + r;
                b[j][0] = wP[n * SP32 + kb];
                b[j][1] = wP[n * SP32 + kb + 4];
            }
#pragma unroll
            for (int i = 0; i < 4; i++)
#pragma unroll
                for (int j = 0; j < 4; j++)
                    mma_f16(acc[i][j], a[i], b[j]);
        }
        __syncthreads();
    }

    int rr = lane >> 2, cc = (lane & 3) * 2;
#pragma unroll
    for (int i = 0; i < 4; i++) {
#pragma unroll
        for (int half = 0; half < 2; half++) {
            int grow = n0 + wm * 64 + i * 16 + rr + half * 8;
#pragma unroll
            for (int j = 0; j < 4; j++) {
                int gcol = m0 + wn * 32 + j * 8 + cc;
                size_t off = (size_t)grow * M + gcol;
                *(float2*)(C + off) =
                    make_float2(acc[i][j][half * 2], acc[i][j][half * 2 + 1]);
            }
        }
    }
}

// ---------------- causal flash attention (fp32, GQA, table RoPE, KV chunk 64) ----------------
__global__ __launch_bounds__(256) void attn_kernel(
    const float* __restrict__ Q, const float* __restrict__ K,
    const float* __restrict__ V,
    __half* __restrict__ Ohi, __half* __restrict__ Olo) {
    __shared__ float Qs[64][64];
    __shared__ float Ks[64][68];
    __shared__ float Vs[64][64];
    __shared__ float Ps[64][65];
    int bh = blockIdx.y;
    int b = bh >> 4;
    int h = bh & 15;
    int kvh = h >> 2;
    int q0 = blockIdx.x * 64;
    int tid = threadIdx.x;
    int lane = tid & 31, warp = tid >> 5;
    const float scale = 0.125f;

    const float* Qbase = Q + ((size_t)(b * SEQ + q0)) * DMODEL + h * HEADDIM;
    for (int i = tid; i < 64 * 8; i += 256) {
        int row = i >> 3, c4 = i & 7;
        int t = q0 + row;
        const float* qp = Qbase + (size_t)row * DMODEL;
        float4 x1 = *(const float4*)(qp + c4 * 4);
        float4 x2 = *(const float4*)(qp + c4 * 4 + 32);
        float4 cv = *(const float4*)&g_rc[t * 32 + c4 * 4];
        float4 sv = *(const float4*)&g_rs[t * 32 + c4 * 4];
        float4 o1, o2;
        float* x1p = &x1.x; float* x2p = &x2.x;
        float* o1p = &o1.x; float* o2p = &o2.x;
        float* cp = &cv.x;  float* spp = &sv.x;
#pragma unroll
        for (int j = 0; j < 4; j++) {
            o1p[j] = (x1p[j] * cp[j] - x2p[j] * spp[j]) * scale;
            o2p[j] = (x2p[j] * cp[j] + x1p[j] * spp[j]) * scale;
        }
        *(float4*)&Qs[row][c4 * 4] = o1;
        *(float4*)&Qs[row][c4 * 4 + 32] = o2;
    }

    float m[8], l[8], acc0[8], acc1[8];
#pragma unroll
    for (int r = 0; r < 8; r++) { m[r] = -1e30f; l[r] = 0.f; acc0[r] = 0.f; acc1[r] = 0.f; }

    int kend = q0 + 64;
    for (int kc = 0; kc < kend; kc += 64) {
        __syncthreads();
        const float* Kbase = K + ((size_t)(b * SEQ + kc)) * KVDIM + kvh * HEADDIM;
        const float* Vbase = V + ((size_t)(b * SEQ + kc)) * KVDIM + kvh * HEADDIM;
        // K tile (64 rows, table RoPE)
        for (int i = tid; i < 64 * 8; i += 256) {
            int row = i >> 3, c4 = i & 7;
            int t = kc + row;
            const float* kp = Kbase + (size_t)row * KVDIM;
            float4 x1 = *(const float4*)(kp + c4 * 4);
            float4 x2 = *(const float4*)(kp + c4 * 4 + 32);
            float4 cv = *(const float4*)&g_rc[t * 32 + c4 * 4];
            float4 sv = *(const float4*)&g_rs[t * 32 + c4 * 4];
            float4 o1, o2;
            float* x1p = &x1.x; float* x2p = &x2.x;
            float* o1p = &o1.x; float* o2p = &o2.x;
            float* cp = &cv.x;  float* spp = &sv.x;
#pragma unroll
            for (int j = 0; j < 4; j++) {
                o1p[j] = x1p[j] * cp[j] - x2p[j] * spp[j];
                o2p[j] = x2p[j] * cp[j] + x1p[j] * spp[j];
            }
            *(float4*)&Ks[row][c4 * 4] = o1;
            *(float4*)&Ks[row][c4 * 4 + 32] = o2;
        }
        // V tile (64 rows, plain)
        for (int i = tid; i < 64 * 16; i += 256) {
            int row = i >> 4, c = (i & 15) * 4;
            float4 vv = *(const float4*)(Vbase + (size_t)row * KVDIM + c);
            *(float4*)&Vs[row][c] = vv;
        }
        __syncthreads();

        // scores: lane owns keys kc+lane and kc+lane+32, 8 rows per warp
        float s0[8] = {0.f, 0.f, 0.f, 0.f, 0.f, 0.f, 0.f, 0.f};
        float s1[8] = {0.f, 0.f, 0.f, 0.f, 0.f, 0.f, 0.f, 0.f};
#pragma unroll
        for (int d4 = 0; d4 < 16; d4++) {
            float4 kv0 = *(const float4*)&Ks[lane][d4 * 4];
            float4 kv1 = *(const float4*)&Ks[lane + 32][d4 * 4];
#pragma unroll
            for (int r = 0; r < 8; r++) {
                float4 qv = *(const float4*)&Qs[warp * 8 + r][d4 * 4];
                s0[r] += qv.x * kv0.x + qv.y * kv0.y + qv.z * kv0.z + qv.w * kv0.w;
                s1[r] += qv.x * kv1.x + qv.y * kv1.y + qv.z * kv1.z + qv.w * kv1.w;
            }
        }
        int key0 = kc + lane;
        int key1 = kc + lane + 32;
#pragma unroll
        for (int r = 0; r < 8; r++) {
            int qrow = q0 + warp * 8 + r;
            float sv0 = (key0 <= qrow) ? s0[r] : -1e30f;
            float sv1 = (key1 <= qrow) ? s1[r] : -1e30f;
            float mx = fmaxf(sv0, sv1);
#pragma unroll
            for (int o = 16; o > 0; o >>= 1) mx = fmaxf(mx, __shfl_xor_sync(0xffffffffu, mx, o));
            float mn = fmaxf(m[r], mx);
            float p0 = __expf(sv0 - mn);
            float p1 = __expf(sv1 - mn);
            float cor = __expf(m[r] - mn);
            float ps = p0 + p1;
#pragma unroll
            for (int o = 16; o > 0; o >>= 1) ps += __shfl_xor_sync(0xffffffffu, ps, o);
            l[r] = l[r] * cor + ps;
            acc0[r] *= cor;
            acc1[r] *= cor;
            m[r] = mn;
            Ps[warp * 8 + r][lane] = p0;
            Ps[warp * 8 + r][lane + 32] = p1;
        }
        __syncwarp();
#pragma unroll 4
        for (int j = 0; j < 64; j++) {
            float v0 = Vs[j][lane];
            float v1 = Vs[j][lane + 32];
#pragma unroll
            for (int r = 0; r < 8; r++) {
                float p = Ps[warp * 8 + r][j];
                acc0[r] += p * v0;
                acc1[r] += p * v1;
            }
        }
    }

    size_t obase = ((size_t)(b * SEQ + q0)) * DMODEL + h * HEADDIM;
#pragma unroll
    for (int r = 0; r < 8; r++) {
        int row = warp * 8 + r;
        float inv = 1.0f / l[r];
        float v0 = acc0[r] * inv, v1 = acc1[r] * inv;
        __half h0, h1, l0, l1;
        hsplit(v0, h0, l0);
        hsplit(v1, h1, l1);
        size_t o0 = obase + (size_t)row * DMODEL + lane;
        Ohi[o0] = h0;  Olo[o0] = l0;
        Ohi[o0 + 32] = h1;  Olo[o0 + 32] = l1;
    }
}

// ---------------- host orchestration ----------------
extern "C" void kernel_launch(void* const* d_in, const int* in_sizes, int n_in,
                              void* d_out, int out_size) {
    const int*   ids = (const int*)d_in[0];
    const float* emb = (const float*)d_in[1];
    const float* ln1 = (const float*)d_in[2];
    const float* qw  = (const float*)d_in[3];
    const float* kw  = (const float*)d_in[4];
    const float* vw  = (const float*)d_in[5];
    const float* ow  = (const float*)d_in[6];
    const float* ln2 = (const float*)d_in[7];
    const float* w1  = (const float*)d_in[8];
    const float* w2  = (const float*)d_in[9];
    const float* w3  = (const float*)d_in[10];
    const float* lnf = (const float*)d_in[11];
    float* out = (float*)d_out;

    float *x, *q, *k, *v, *gate, *p0, *p1, *rc, *rs;
    __half *hh, *hl, *oh, *ol, *uph, *upl;
    __half *embw, *qww, *kww, *vww, *owh, *owl, *w1w, *w2w, *w3w;
    cudaGetSymbolAddress((void**)&x, g_x);
    cudaGetSymbolAddress((void**)&q, g_q);
    cudaGetSymbolAddress((void**)&k, g_k);
    cudaGetSymbolAddress((void**)&v, g_v);
    cudaGetSymbolAddress((void**)&gate, g_gate);
    cudaGetSymbolAddress((void**)&p0, g_p0);
    cudaGetSymbolAddress((void**)&p1, g_p1);
    cudaGetSymbolAddress((void**)&rc, g_rc);
    cudaGetSymbolAddress((void**)&rs, g_rs);
    cudaGetSymbolAddress((void**)&hh, g_h_h);
    cudaGetSymbolAddress((void**)&hl, g_h_l);
    cudaGetSymbolAddress((void**)&oh, g_o_h);
    cudaGetSymbolAddress((void**)&ol, g_o_l);
    cudaGetSymbolAddress((void**)&uph, g_up_h);
    cudaGetSymbolAddress((void**)&upl, g_up_l);
    cudaGetSymbolAddress((void**)&embw, s_emb_w);
    cudaGetSymbolAddress((void**)&qww, s_qw_w);
    cudaGetSymbolAddress((void**)&kww, s_kw_w);
    cudaGetSymbolAddress((void**)&vww, s_vw_w);
    cudaGetSymbolAddress((void**)&owh, s_ow_h);
    cudaGetSymbolAddress((void**)&owl, s_ow_l);
    cudaGetSymbolAddress((void**)&w1w, s_w1_w);
    cudaGetSymbolAddress((void**)&w2w, s_w2_w);
    cudaGetSymbolAddress((void**)&w3w, s_w3_w);

    cudaFuncSetAttribute(gemm2_k<0>, cudaFuncAttributeMaxDynamicSharedMemorySize, SM_G2);
    cudaFuncSetAttribute(gemm2_k<2>, cudaFuncAttributeMaxDynamicSharedMemorySize, SM_G2);
    cudaFuncSetAttribute(gemm2_k<3>, cudaFuncAttributeMaxDynamicSharedMemorySize, SM_G2);
    cudaFuncSetAttribute(gemm2p_k,   cudaFuncAttributeMaxDynamicSharedMemorySize, SM_G2);
    cudaFuncSetAttribute(gemm3p_k,   cudaFuncAttributeMaxDynamicSharedMemorySize, SM_G3);
    cudaFuncSetAttribute(gemm1_k,    cudaFuncAttributeMaxDynamicSharedMemorySize, SM_G1);
    cudaFuncSetAttribute(gemm_qkv,   cudaFuncAttributeMaxDynamicSharedMemorySize, SM_G2);

    // pre-pass: weights -> f16 planes, RoPE tables
    rope_table_kernel<<<SEQ * 32 / 256, 256>>>(rc, rs);
    split_w_kernel<<<EMB_N / 1024, 256>>>(emb, embw);
    split_w_kernel<<<QW_N / 1024, 256>>>(qw, qww);
    split_w_kernel<<<KW_N / 1024, 256>>>(kw, kww);
    split_w_kernel<<<KW_N / 1024, 256>>>(vw, vww);
    split_w2_kernel<<<QW_N / 1024, 256>>>(ow, owh, owl);
    split_w_kernel<<<W1_N / 1024, 256>>>(w1, w1w);
    split_w_kernel<<<W1_N / 1024, 256>>>(w2, w2w);
    split_w_kernel<<<W1_N / 1024, 256>>>(w3, w3w);

    embed_kernel<<<NTOK, 256>>>(ids, emb, x);

    const int TB = NTOK / 128;   // 16 token blocks: FAST grid dim (weight L2 reuse)
    for (int l = 0; l < NLAYER; l++) {
        size_t qo = (size_t)l * DMODEL * DMODEL;
        size_t ko = (size_t)l * KVDIM * DMODEL;
        size_t fo = (size_t)l * FFN * DMODEL;

        // ln1: merge previous layer's w2 partials (layer 0: plain)
        if (l == 0)
            rmsnorm_split_kernel<<<NTOK, 256>>>(x, ln1, hh, hl);
        else
            rmsnorm_merge_split_kernel<<<NTOK, 256>>>(x, p0, p1,
                                                      ln1 + l * DMODEL, hh, hl);
        gemm_qkv<<<dim3(TB, 12), 256, SM_G2>>>(
            hh, hl, qww + qo, kww + ko, vww + ko, q, k, v);
        attn_kernel<<<dim3(SEQ / 64, 2 * NHEAD), 256>>>(q, k, v, oh, ol);
        // o_proj: split-K=2 partials
        gemm3p_k<<<dim3(TB, DMODEL / 128, 2), 256, SM_G3>>>(
            oh, ol, owh + qo, owl + qo, p0, p1, DMODEL, DMODEL);
        // ln2: merge o_proj partials into x
        rmsnorm_merge_split_kernel<<<NTOK, 256>>>(x, p0, p1,
                                                  ln2 + l * DMODEL, hh, hl);
        gemm2_k<2><<<dim3(TB, FFN / 128), 256, SM_G2>>>(
            hh, hl, w1w + fo, gate, nullptr, nullptr, nullptr, DMODEL, FFN);
        gemm2_k<3><<<dim3(TB, FFN / 128), 256, SM_G2>>>(
            hh, hl, w3w + fo, nullptr, gate, uph, upl, DMODEL, FFN);
        // w2: split-K=2 partials (merged at next ln1 or lnf)
        gemm2p_k<<<dim3(TB, DMODEL / 128, 2), 256, SM_G2>>>(
            uph, upl, w2w + fo, p0, p1, FFN, DMODEL);
    }

    // lnf: merge last layer's w2 partials
    rmsnorm_merge_split_kernel<<<NTOK, 256>>>(x, p0, p1, lnf, hh, hl);
    gemm1_k<<<dim3(TB, VOCAB / 128), 256, SM_G1>>>(hh, embw, out, DMODEL, VOCAB);
}